// round 11
// baseline (speedup 1.0000x reference)
#include <cuda_runtime.h>
#include <cuda_bf16.h>
#include <cstdint>
#include <cstddef>

#define NN 50000
#define EE 800000
#define CC 128

// ---------------- device globals ----------------
__device__ float g_aggc[NN * CC];
__device__ float g_agge[NN * CC];
__device__ float g_deg[NN];
__device__ float g_x1[NN * CC];     // L0: xwr scratch ; L1: x1 output
__device__ float g_x2[NN * CC];
__device__ float g_n2a[NN], g_s1a[NN], g_n2b[NN], g_s1b[NN];
__device__ __align__(16) char g_wt[5][2][32768];  // 0=Wr0 1=Wl0 2=Wr1 3=Wl1 4=attW1

// ---------------- helpers ----------------
__device__ __forceinline__ float wsum(float v) {
#pragma unroll
    for (int o = 16; o; o >>= 1) v += __shfl_xor_sync(0xFFFFFFFFu, v, o);
    return v;
}
__device__ __forceinline__ void red_v4(float* p, float a, float b, float c, float d) {
    asm volatile("red.global.add.v4.f32 [%0], {%1,%2,%3,%4};"
                 :: "l"(__cvta_generic_to_global(p)), "f"(a), "f"(b), "f"(c), "f"(d)
                 : "memory");
}
__device__ __forceinline__ uint32_t smem_u32(const void* p) {
    uint32_t a;
    asm("{ .reg .u64 t; cvta.to.shared.u64 t, %1; cvt.u32.u64 %0, t; }" : "=r"(a) : "l"(p));
    return a;
}
__device__ __forceinline__ float tanha(float x) {
    float y; asm("tanh.approx.f32 %0, %1;" : "=f"(y) : "f"(x)); return y;
}
__device__ __forceinline__ uint32_t pack2(float x, float y, uint32_t& lo) {
    uint32_t h;
    asm("cvt.rn.bf16x2.f32 %0, %1, %2;" : "=r"(h) : "f"(y), "f"(x));
    float hx = __uint_as_float(h << 16);
    float hy = __uint_as_float(h & 0xFFFF0000u);
    float rx = x - hx, ry = y - hy;
    asm("cvt.rn.bf16x2.f32 %0, %1, %2;" : "=r"(lo) : "f"(ry), "f"(rx));
    return h;
}
__device__ __forceinline__ void ldsm4(uint32_t (&r)[4], uint32_t addr) {
    asm volatile("ldmatrix.sync.aligned.m8n8.x4.shared.b16 {%0,%1,%2,%3}, [%4];"
                 : "=r"(r[0]), "=r"(r[1]), "=r"(r[2]), "=r"(r[3]) : "r"(addr));
}
__device__ __forceinline__ void mma_bf16(float (&d)[4], const uint32_t (&a)[4],
                                         uint32_t b0, uint32_t b1) {
    asm volatile("mma.sync.aligned.m16n8k16.row.col.f32.bf16.bf16.f32 "
                 "{%0,%1,%2,%3}, {%4,%5,%6,%7}, {%8,%9}, {%0,%1,%2,%3};"
                 : "+f"(d[0]), "+f"(d[1]), "+f"(d[2]), "+f"(d[3])
                 : "r"(a[0]), "r"(a[1]), "r"(a[2]), "r"(a[3]), "r"(b0), "r"(b1));
}
__device__ __forceinline__ uint32_t tile_off(int row, int chunk) {
    return (uint32_t)(row * 256 + (((chunk ^ (row & 7)) & 15) << 4));
}

// ---------------- smem layouts ----------------
#define S_AH 1024
#define S_AL (S_AH + 32768)
#define S_B  (S_AL + 32768)
#define SMEM_G (S_B + 32768)          // 99328 (2 CTA/SM)
#define SA_WH (S_AL + 32768)
#define SA_WL (SA_WH + 16384)
#define SA_WSM (SA_WL + 16384)
#define SMEM_A (SA_WSM + 2048)       // 101376

// A tile conversion: 128 rows x 128 fp32 -> hi/lo bf16 swizzled, optional 1/deg scale
__device__ __forceinline__ void convA128(char* sm, const float* __restrict__ src,
                                         int bm, const float* __restrict__ deg, int tid) {
    int r = tid >> 1, half = tid & 1;
    int gr = bm + r;
    bool valid = gr < NN;
    float sc = 1.0f;
    if (deg != nullptr && valid) sc = 1.0f / fmaxf(deg[gr], 1.0f);
    const float4* s4 = (const float4*)(src + (size_t)(valid ? gr : 0) * CC + half * 64);
#pragma unroll
    for (int i = 0; i < 8; ++i) {
        float4 v0 = make_float4(0.f, 0.f, 0.f, 0.f), v1 = v0;
        if (valid) { v0 = s4[2 * i]; v1 = s4[2 * i + 1]; }
        v0.x *= sc; v0.y *= sc; v0.z *= sc; v0.w *= sc;
        v1.x *= sc; v1.y *= sc; v1.z *= sc; v1.w *= sc;
        uint4 H, L;
        H.x = pack2(v0.x, v0.y, L.x);
        H.y = pack2(v0.z, v0.w, L.y);
        H.z = pack2(v1.x, v1.y, L.z);
        H.w = pack2(v1.z, v1.w, L.w);
        uint32_t off = tile_off(r, half * 8 + i);
        *(uint4*)(sm + S_AH + off) = H;
        *(uint4*)(sm + S_AL + off) = L;
    }
}
__device__ __forceinline__ void copyB32(char* sm, const char* __restrict__ src, int tid) {
    const uint4* s = (const uint4*)src;
    uint4* d = (uint4*)(sm + S_B);
#pragma unroll
    for (int i = 0; i < 8; ++i) d[tid + i * 256] = s[tid + i * 256];
}

// one bf16 term over K=128 for a 32x64 warp tile
__device__ __forceinline__ void warp_term32(uint32_t aBase, uint32_t bBase,
                                            int wm, int wn, int lane, float (&acc)[16][4]) {
    int quad = lane >> 3, l7 = lane & 7;
    uint32_t arb[2]; int ar7[2];
    int acoff = quad >> 1;
#pragma unroll
    for (int mt = 0; mt < 2; ++mt) {
        int row = wm + mt * 16 + (quad & 1) * 8 + l7;
        arb[mt] = (uint32_t)(row * 256); ar7[mt] = row & 7;
    }
    uint32_t brb[4]; int br7[4];
    int bcoff = quad & 1;
#pragma unroll
    for (int j = 0; j < 4; ++j) {
        int row = wn + j * 16 + (quad >> 1) * 8 + l7;
        brb[j] = (uint32_t)(row * 256); br7[j] = row & 7;
    }
#pragma unroll
    for (int ks = 0; ks < 8; ++ks) {
        uint32_t a[2][4];
#pragma unroll
        for (int mt = 0; mt < 2; ++mt)
            ldsm4(a[mt], aBase + arb[mt] + ((((2 * ks + acoff) ^ ar7[mt]) & 15) << 4));
        uint32_t b[4][4];
#pragma unroll
        for (int j = 0; j < 4; ++j)
            ldsm4(b[j], bBase + brb[j] + ((((2 * ks + bcoff) ^ br7[j]) & 15) << 4));
#pragma unroll
        for (int mt = 0; mt < 2; ++mt)
#pragma unroll
            for (int nt = 0; nt < 8; ++nt)
                mma_bf16(acc[mt * 8 + nt], a[mt],
                         b[nt >> 1][(nt & 1) * 2], b[nt >> 1][(nt & 1) * 2 + 1]);
    }
}
// one bf16 term for a 16x64 warp tile (attention)
__device__ __forceinline__ void warp_term16(uint32_t aBase, uint32_t bBase,
                                            int wm, int lane, float (&acc)[8][4]) {
    int quad = lane >> 3, l7 = lane & 7;
    int arow = wm + (quad & 1) * 8 + l7;
    uint32_t arb = (uint32_t)(arow * 256); int ar7 = arow & 7;
    int acoff = quad >> 1;
    uint32_t brb[4]; int br7[4];
    int bcoff = quad & 1;
#pragma unroll
    for (int j = 0; j < 4; ++j) {
        int row = j * 16 + (quad >> 1) * 8 + l7;
        brb[j] = (uint32_t)(row * 256); br7[j] = row & 7;
    }
#pragma unroll
    for (int ks = 0; ks < 8; ++ks) {
        uint32_t a[4];
        ldsm4(a, aBase + arb + ((((2 * ks + acoff) ^ ar7) & 15) << 4));
        uint32_t b[4][4];
#pragma unroll
        for (int j = 0; j < 4; ++j)
            ldsm4(b[j], bBase + brb[j] + ((((2 * ks + bcoff) ^ br7[j]) & 15) << 4));
#pragma unroll
        for (int nt = 0; nt < 8; ++nt)
            mma_bf16(acc[nt], a, b[nt >> 1][(nt & 1) * 2], b[nt >> 1][(nt & 1) * 2 + 1]);
    }
}

// ---------------- weight pre-conversion (grid (5,4)) ----------------
__global__ void convw_k(const float* W0, const float* W1, const float* W2,
                        const float* W3, const float* W4) {
    const float* W; int N;
    switch (blockIdx.x) {
        case 0: W = W0; N = 128; break;
        case 1: W = W1; N = 128; break;
        case 2: W = W2; N = 128; break;
        case 3: W = W3; N = 128; break;
        default: W = W4; N = 64; break;
    }
    int tid = threadIdx.x;
    int n = tid >> 1, half = tid & 1;
    if (n >= N) return;
    char* dh = g_wt[blockIdx.x][0];
    char* dl = g_wt[blockIdx.x][1];
    int i0 = blockIdx.y * 2;
#pragma unroll
    for (int i = i0; i < i0 + 2; ++i) {
        int k = (half * 8 + i) * 8;
        float v[8];
#pragma unroll
        for (int j = 0; j < 8; ++j) v[j] = __ldg(W + (size_t)(k + j) * N + n);
        uint4 H, L;
        H.x = pack2(v[0], v[1], L.x);
        H.y = pack2(v[2], v[3], L.y);
        H.z = pack2(v[4], v[5], L.z);
        H.w = pack2(v[6], v[7], L.w);
        uint32_t off = tile_off(n, half * 8 + i);
        *(uint4*)(dh + off) = H;
        *(uint4*)(dl + off) = L;
    }
}

// ---------------- gemm_one: O = A@W + bias (no relu) ----------------
__global__ void __launch_bounds__(256, 2) gemm_one(
    const float* __restrict__ A, int w, const float* __restrict__ bias,
    float* __restrict__ O)
{
    extern __shared__ char sm[];
    int tid = threadIdx.x, lane = tid & 31, wid = tid >> 5;
    int bm = blockIdx.x * 128;
    uint32_t smb = smem_u32(sm);
    float* sbias = (float*)sm;
    if (tid < 128) sbias[tid] = bias[tid];

    float acc[16][4];
#pragma unroll
    for (int i = 0; i < 16; ++i)
#pragma unroll
        for (int j = 0; j < 4; ++j) acc[i][j] = 0.f;

    const int wm = (wid & 3) * 32, wn = (wid >> 2) * 64;

    convA128(sm, A, bm, nullptr, tid);
    copyB32(sm, g_wt[w][0], tid);
    __syncthreads();
    warp_term32(smb + S_AH, smb + S_B, wm, wn, lane, acc);
    warp_term32(smb + S_AL, smb + S_B, wm, wn, lane, acc);
    __syncthreads();
    copyB32(sm, g_wt[w][1], tid);
    __syncthreads();
    warp_term32(smb + S_AH, smb + S_B, wm, wn, lane, acc);

    int g = lane >> 2, tg = lane & 3;
#pragma unroll
    for (int mt = 0; mt < 2; ++mt) {
        int m0 = bm + wm + mt * 16 + g;
#pragma unroll
        for (int nt = 0; nt < 8; ++nt) {
            int cl = wn + nt * 8 + tg * 2;
            float b0 = sbias[cl], b1 = sbias[cl + 1];
            int idx = mt * 8 + nt;
            if (m0 < NN) {
                float2 v;
                v.x = acc[idx][0] + b0; v.y = acc[idx][1] + b1;
                *(float2*)(O + (size_t)m0 * CC + cl) = v;
            }
            if (m0 + 8 < NN) {
                float2 v;
                v.x = acc[idx][2] + b0; v.y = acc[idx][3] + b1;
                *(float2*)(O + (size_t)(m0 + 8) * CC + cl) = v;
            }
        }
    }
}

// ---------------- gemm_cadd: O[br] = relu(agg[br]/deg @ W + Cadd) ----------------
__global__ void __launch_bounds__(256, 2) gemm_cadd(
    int w, const float* __restrict__ Cadd,
    float* __restrict__ Oc, float* __restrict__ Oe)
{
    extern __shared__ char sm[];
    int tid = threadIdx.x, lane = tid & 31, wid = tid >> 5;
    int bm = blockIdx.x * 128, br = blockIdx.y;
    uint32_t smb = smem_u32(sm);
    const float* A = br ? g_agge : g_aggc;
    float* O = br ? Oe : Oc;

    float acc[16][4];
#pragma unroll
    for (int i = 0; i < 16; ++i)
#pragma unroll
        for (int j = 0; j < 4; ++j) acc[i][j] = 0.f;

    const int wm = (wid & 3) * 32, wn = (wid >> 2) * 64;

    convA128(sm, A, bm, g_deg, tid);
    copyB32(sm, g_wt[w][0], tid);
    __syncthreads();
    warp_term32(smb + S_AH, smb + S_B, wm, wn, lane, acc);
    warp_term32(smb + S_AL, smb + S_B, wm, wn, lane, acc);
    __syncthreads();
    copyB32(sm, g_wt[w][1], tid);
    __syncthreads();
    warp_term32(smb + S_AH, smb + S_B, wm, wn, lane, acc);

    int g = lane >> 2, tg = lane & 3;
#pragma unroll
    for (int mt = 0; mt < 2; ++mt) {
        int m0 = bm + wm + mt * 16 + g;
#pragma unroll
        for (int nt = 0; nt < 8; ++nt) {
            int cl = wn + nt * 8 + tg * 2;
            int idx = mt * 8 + nt;
            if (m0 < NN) {
                float2 cv = *(const float2*)(Cadd + (size_t)m0 * CC + cl);
                float2 v;
                v.x = fmaxf(acc[idx][0] + cv.x, 0.f);
                v.y = fmaxf(acc[idx][1] + cv.y, 0.f);
                *(float2*)(O + (size_t)m0 * CC + cl) = v;
            }
            if (m0 + 8 < NN) {
                float2 cv = *(const float2*)(Cadd + (size_t)(m0 + 8) * CC + cl);
                float2 v;
                v.x = fmaxf(acc[idx][2] + cv.x, 0.f);
                v.y = fmaxf(acc[idx][3] + cv.y, 0.f);
                *(float2*)(O + (size_t)(m0 + 8) * CC + cl) = v;
            }
        }
    }
}

// ---------------- L1 fused GEMM (R8 proven): O[br] = A1@W1 + A2/deg@W2 + bias ---------
__global__ void __launch_bounds__(256, 2) gemm_two(
    const float* __restrict__ A1c, const float* __restrict__ A1e,
    int w1, int w2, const float* __restrict__ bias,
    float* __restrict__ Oc, float* __restrict__ Oe)
{
    extern __shared__ char sm[];
    int tid = threadIdx.x, lane = tid & 31, wid = tid >> 5;
    int bm = blockIdx.x * 128, br = blockIdx.y;
    uint32_t smb = smem_u32(sm);
    float* sbias = (float*)sm;
    if (tid < 128) sbias[tid] = bias[tid];
    const float* A1 = br ? A1e : A1c;
    const float* A2 = br ? g_agge : g_aggc;
    float* O = br ? Oe : Oc;

    float acc[16][4];
#pragma unroll
    for (int i = 0; i < 16; ++i)
#pragma unroll
        for (int j = 0; j < 4; ++j) acc[i][j] = 0.f;

    const int wm = (wid & 3) * 32, wn = (wid >> 2) * 64;

    for (int pass = 0; pass < 2; ++pass) {
        const float* A = pass ? A2 : A1;
        const float* dg = pass ? g_deg : nullptr;
        int w = pass ? w2 : w1;
        convA128(sm, A, bm, dg, tid);
        copyB32(sm, g_wt[w][0], tid);
        __syncthreads();
        warp_term32(smb + S_AH, smb + S_B, wm, wn, lane, acc);
        warp_term32(smb + S_AL, smb + S_B, wm, wn, lane, acc);
        __syncthreads();
        copyB32(sm, g_wt[w][1], tid);
        __syncthreads();
        warp_term32(smb + S_AH, smb + S_B, wm, wn, lane, acc);
        __syncthreads();
    }

    int g = lane >> 2, tg = lane & 3;
#pragma unroll
    for (int mt = 0; mt < 2; ++mt) {
        int m0 = bm + wm + mt * 16 + g;
#pragma unroll
        for (int nt = 0; nt < 8; ++nt) {
            int cl = wn + nt * 8 + tg * 2;
            float b0 = sbias[cl], b1 = sbias[cl + 1];
            int idx = mt * 8 + nt;
            if (m0 < NN) {
                float2 v;
                v.x = acc[idx][0] + b0; v.y = acc[idx][1] + b1;
                *(float2*)(O + (size_t)m0 * CC + cl) = v;
            }
            if (m0 + 8 < NN) {
                float2 v;
                v.x = acc[idx][2] + b0; v.y = acc[idx][3] + b1;
                *(float2*)(O + (size_t)(m0 + 8) * CC + cl) = v;
            }
        }
    }
}

// ---------------- per-node norm2/sum ----------------
__global__ void __launch_bounds__(256) pre_k(const float* __restrict__ X,
                                             float* __restrict__ n2, float* __restrict__ s1) {
    int node = blockIdx.x * 8 + (threadIdx.x >> 5);
    if (node >= NN) return;
    int lane = threadIdx.x & 31;
    float4 v = *(const float4*)(X + (size_t)node * CC + lane * 4);
    float n = wsum(v.x * v.x + v.y * v.y + v.z * v.z + v.w * v.w);
    float s = wsum(v.x + v.y + v.z + v.w);
    if (lane == 0) { n2[node] = n; s1[node] = s; }
}
// fused: n2a <- |x3|^2 ; n2b,s1b <- |x4|^2, sum(x4)
__global__ void __launch_bounds__(256) pre2_k(const float* __restrict__ X3,
                                              const float* __restrict__ X4) {
    int node = blockIdx.x * 8 + (threadIdx.x >> 5);
    if (node >= NN) return;
    int lane = threadIdx.x & 31;
    float4 a = *(const float4*)(X3 + (size_t)node * CC + lane * 4);
    float4 b = *(const float4*)(X4 + (size_t)node * CC + lane * 4);
    float n3 = a.x * a.x + a.y * a.y + a.z * a.z + a.w * a.w;
    float n4 = b.x * b.x + b.y * b.y + b.z * b.z + b.w * b.w;
    float s4 = b.x + b.y + b.z + b.w;
#pragma unroll
    for (int o = 16; o; o >>= 1) {
        n3 += __shfl_xor_sync(0xFFFFFFFFu, n3, o);
        n4 += __shfl_xor_sync(0xFFFFFFFFu, n4, o);
        s4 += __shfl_xor_sync(0xFFFFFFFFu, s4, o);
    }
    if (lane == 0) { g_n2a[node] = n3; g_n2b[node] = n4; g_s1b[node] = s4; }
}

// ---------------- edge pass 1 ----------------
__global__ void __launch_bounds__(256) edge1_k(const float* __restrict__ x,
                                               const int* __restrict__ row,
                                               const int* __restrict__ col) {
    int e = blockIdx.x * 8 + (threadIdx.x >> 5);
    if (e >= EE) return;
    int lane = threadIdx.x & 31;
    int r = __ldg(row + e), c = __ldg(col + e);
    float4 a = *(const float4*)(x + (size_t)r * CC + lane * 4);
    float4 b = *(const float4*)(x + (size_t)c * CC + lane * 4);
    float d = wsum(a.x * b.x + a.y * b.y + a.z * b.z + a.w * b.w);
    float na = __ldg(g_n2a + r), nb = __ldg(g_n2a + c);
    float sa = __ldg(g_s1a + r), sb = __ldg(g_s1a + c);
    float ecos = d / fmaxf(sqrtf(na * nb), 1e-8f);
    float t = na + nb - 2.f * d + 2e-6f * (sa - sb) + 1.28e-10f;
    float eeud = sqrtf(fmaxf(t, 0.f));
    size_t off = (size_t)r * CC + lane * 4;
    red_v4(g_aggc + off, ecos * b.x, ecos * b.y, ecos * b.z, ecos * b.w);
    red_v4(g_agge + off, eeud * b.x, eeud * b.y, eeud * b.z, eeud * b.w);
    if (lane == 0)
        asm volatile("red.global.add.f32 [%0], %1;"
                     :: "l"(__cvta_generic_to_global(g_deg + r)), "f"(1.0f) : "memory");
}

// ---------------- edge pass 2 ----------------
__global__ void __launch_bounds__(256) edge2_k(const float* __restrict__ x3,
                                               const float* __restrict__ x4,
                                               const int* __restrict__ row,
                                               const int* __restrict__ col) {
    int e = blockIdx.x * 8 + (threadIdx.x >> 5);
    if (e >= EE) return;
    int lane = threadIdx.x & 31;
    int r = __ldg(row + e), c = __ldg(col + e);
    size_t ro = (size_t)r * CC + lane * 4;
    size_t co = (size_t)c * CC + lane * 4;
    float4 a3 = *(const float4*)(x3 + ro);
    float4 b3 = *(const float4*)(x3 + co);
    float4 a4 = *(const float4*)(x4 + ro);
    float4 b4 = *(const float4*)(x4 + co);
    float d3 = a3.x * b3.x + a3.y * b3.y + a3.z * b3.z + a3.w * b3.w;
    float d4 = a4.x * b4.x + a4.y * b4.y + a4.z * b4.z + a4.w * b4.w;
#pragma unroll
    for (int o = 16; o; o >>= 1) {
        d3 += __shfl_xor_sync(0xFFFFFFFFu, d3, o);
        d4 += __shfl_xor_sync(0xFFFFFFFFu, d4, o);
    }
    float n3a = __ldg(g_n2a + r), n3b = __ldg(g_n2a + c);
    float n4a = __ldg(g_n2b + r), n4b = __ldg(g_n2b + c);
    float s4a = __ldg(g_s1b + r), s4b = __ldg(g_s1b + c);
    float ecos = d3 / fmaxf(sqrtf(n3a * n3b), 1e-8f);
    float t = n4a + n4b - 2.f * d4 + 2e-6f * (s4a - s4b) + 1.28e-10f;
    float eeud = sqrtf(fmaxf(t, 0.f));
    red_v4(g_aggc + ro, ecos * b3.x, ecos * b3.y, ecos * b3.z, ecos * b3.w);
    red_v4(g_agge + ro, eeud * b4.x, eeud * b4.y, eeud * b4.z, eeud * b4.w);
}

// ---------------- attention: tensor-core logits + softmax blend ----------------
__global__ void __launch_bounds__(256) att_tc(
    const float* __restrict__ x1, const float* __restrict__ x2,
    const float* __restrict__ x3, const float* __restrict__ x4,
    const float* __restrict__ ab1, const float* __restrict__ aW2,
    float* __restrict__ emb)
{
    extern __shared__ char sm[];
    int tid = threadIdx.x, lane = tid & 31, wid = tid >> 5;
    int bm = blockIdx.x * 128;
    uint32_t smb = smem_u32(sm);
    float* b1s = (float*)sm;
    float* w2s = (float*)(sm + 256);
    float* wsm = (float*)(sm + SA_WSM);
    if (tid < 64) { b1s[tid] = ab1[tid]; w2s[tid] = aW2[tid]; }
    {
        const uint4* sh = (const uint4*)g_wt[4][0];
        const uint4* sl = (const uint4*)g_wt[4][1];
        uint4* dh = (uint4*)(sm + SA_WH);
        uint4* dl = (uint4*)(sm + SA_WL);
#pragma unroll
        for (int i = 0; i < 4; ++i) {
            dh[tid + i * 256] = sh[tid + i * 256];
            dl[tid + i * 256] = sl[tid + i * 256];
        }
    }
    const float* Xb[4] = {x1, x2, x3, x4};
    int wm = wid * 16;
    int g = lane >> 2, tg = lane & 3;
    for (int b = 0; b < 4; ++b) {
        __syncthreads();
        convA128(sm, Xb[b], bm, nullptr, tid);
        __syncthreads();
        float acc[8][4];
#pragma unroll
        for (int i = 0; i < 8; ++i)
#pragma unroll
            for (int j = 0; j < 4; ++j) acc[i][j] = 0.f;
        warp_term16(smb + S_AH, smb + SA_WH, wm, lane, acc);
        warp_term16(smb + S_AH, smb + SA_WL, wm, lane, acc);
        warp_term16(smb + S_AL, smb + SA_WH, wm, lane, acc);
        float w0 = 0.f, w1p = 0.f;
#pragma unroll
        for (int nt = 0; nt < 8; ++nt) {
            int cl = nt * 8 + tg * 2;
            w0  += tanha(acc[nt][0] + b1s[cl]) * w2s[cl]
                 + tanha(acc[nt][1] + b1s[cl + 1]) * w2s[cl + 1];
            w1p += tanha(acc[nt][2] + b1s[cl]) * w2s[cl]
                 + tanha(acc[nt][3] + b1s[cl + 1]) * w2s[cl + 1];
        }
        w0 += __shfl_xor_sync(0xFFFFFFFFu, w0, 1);
        w0 += __shfl_xor_sync(0xFFFFFFFFu, w0, 2);
        w1p += __shfl_xor_sync(0xFFFFFFFFu, w1p, 1);
        w1p += __shfl_xor_sync(0xFFFFFFFFu, w1p, 2);
        if (tg == 0) {
            wsm[(wm + g) * 4 + b] = w0;
            wsm[(wm + 8 + g) * 4 + b] = w1p;
        }
    }
    __syncthreads();
    int row = tid >> 1, half = tid & 1;
    int gr = bm + row;
    if (gr >= NN) return;
    float l0 = wsm[row * 4 + 0], l1 = wsm[row * 4 + 1];
    float l2 = wsm[row * 4 + 2], l3 = wsm[row * 4 + 3];
    float m = fmaxf(fmaxf(l0, l1), fmaxf(l2, l3));
    float e0 = __expf(l0 - m), e1 = __expf(l1 - m), e2 = __expf(l2 - m), e3 = __expf(l3 - m);
    float inv = 1.f / (e0 + e1 + e2 + e3);
    float be0 = e0 * inv, be1 = e1 * inv, be2 = e2 * inv, be3 = e3 * inv;
    size_t base = (size_t)gr * CC + half * 64;
#pragma unroll
    for (int c = 0; c < 16; ++c) {
        float4 z0 = *(const float4*)(x1 + base + c * 4);
        float4 z1 = *(const float4*)(x2 + base + c * 4);
        float4 z2 = *(const float4*)(x3 + base + c * 4);
        float4 z3 = *(const float4*)(x4 + base + c * 4);
        float4 o;
        o.x = be0 * z0.x + be1 * z1.x + be2 * z2.x + be3 * z3.x;
        o.y = be0 * z0.y + be1 * z1.y + be2 * z2.y + be3 * z3.y;
        o.z = be0 * z0.z + be1 * z1.z + be2 * z2.z + be3 * z3.z;
        o.w = be0 * z0.w + be1 * z1.w + be2 * z2.w + be3 * z3.w;
        *(float4*)(emb + base + c * 4) = o;
    }
}

// ---------------- launch ----------------
extern "C" void kernel_launch(void* const* d_in, const int* in_sizes, int n_in,
                              void* d_out, int out_size)
{
    const float* x   = (const float*)d_in[0];
    const int*   row = (const int*)d_in[1];
    const int*   col = (const int*)d_in[2];
    const float* Wl0 = (const float*)d_in[3];
    const float* bl0 = (const float*)d_in[4];
    const float* Wr0 = (const float*)d_in[5];
    const float* Wl1 = (const float*)d_in[6];
    const float* bl1 = (const float*)d_in[7];
    const float* Wr1 = (const float*)d_in[8];
    const float* aW1 = (const float*)d_in[9];
    const float* ab1 = (const float*)d_in[10];
    const float* aW2 = (const float*)d_in[11];

    float* out = (float*)d_out;
    float* x3  = out + (size_t)NN * CC;
    float* x4  = out + 2 * (size_t)NN * CC;

    float *aggc, *agge, *deg, *x1, *x2, *n2a, *s1a;
    cudaGetSymbolAddress((void**)&aggc, g_aggc);
    cudaGetSymbolAddress((void**)&agge, g_agge);
    cudaGetSymbolAddress((void**)&deg,  g_deg);
    cudaGetSymbolAddress((void**)&x1,   g_x1);
    cudaGetSymbolAddress((void**)&x2,   g_x2);
    cudaGetSymbolAddress((void**)&n2a,  g_n2a);
    cudaGetSymbolAddress((void**)&s1a,  g_s1a);

    cudaFuncSetAttribute(gemm_one,  cudaFuncAttributeMaxDynamicSharedMemorySize, SMEM_G);
    cudaFuncSetAttribute(gemm_cadd, cudaFuncAttributeMaxDynamicSharedMemorySize, SMEM_G);
    cudaFuncSetAttribute(gemm_two,  cudaFuncAttributeMaxDynamicSharedMemorySize, SMEM_G);
    cudaFuncSetAttribute(att_tc,    cudaFuncAttributeMaxDynamicSharedMemorySize, SMEM_A);

    const int gN = (NN + 7) / 8;           // 6250
    const int ge = (EE + 7) / 8;           // 100000
    const int gG = (NN + 127) / 128;       // 391
    const dim3 gG2(gG, 2);
    const size_t agg_bytes = (size_t)NN * CC * sizeof(float);

    // zero accumulators
    cudaMemsetAsync(deg,  0, NN * sizeof(float));
    cudaMemsetAsync(aggc, 0, agg_bytes);
    cudaMemsetAsync(agge, 0, agg_bytes);

    // weights -> bf16 hi/lo tiles
    convw_k<<<dim3(5, 4), 256>>>(Wr0, Wl0, Wr1, Wl1, aW1);

    // layer 0
    pre_k<<<gN, 256>>>(x, n2a, s1a);
    edge1_k<<<ge, 256>>>(x, row, col);
    gemm_one<<<gG, 256, SMEM_G>>>(x, 0, bl0, x1);              // xwr = x@Wr0 + bl0
    gemm_cadd<<<gG2, 256, SMEM_G>>>(1, x1, x3, x4);            // relu(agg/deg@Wl0 + xwr)

    // layer 1
    cudaMemsetAsync(aggc, 0, agg_bytes);
    cudaMemsetAsync(agge, 0, agg_bytes);
    pre2_k<<<gN, 256>>>(x3, x4);
    edge2_k<<<ge, 256>>>(x3, x4, row, col);
    gemm_two<<<gG2, 256, SMEM_G>>>(x3, x4, 2, 3, bl1, x1, x2); // x1/x2 outputs

    // attention
    att_tc<<<gG, 256, SMEM_A>>>(x1, x2, x3, x4, ab1, aW2, out);
}

// round 12
// speedup vs baseline: 1.6621x; 1.6621x over previous
#include <cuda_runtime.h>
#include <cuda_bf16.h>
#include <cstdint>
#include <cstddef>

#define NN 50000
#define EE 800000
#define CC 128

// ---------------- device globals ----------------
__device__ float g_aggc[NN * CC];
__device__ float g_agge[NN * CC];
__device__ float g_x1[NN * CC];     // L0: xwr scratch ; L1: x1 output
__device__ float g_x2[NN * CC];
__device__ float g_n2a[NN], g_s1a[NN], g_n2b[NN], g_s1b[NN];
__device__ int   g_ptr[NN + 1];
__device__ int   g_cnt[NN];
__device__ int   g_adj[EE];
__device__ __align__(16) char g_wt[5][2][32768];  // 0=Wr0 1=Wl0 2=Wr1 3=Wl1 4=attW1

// ---------------- helpers ----------------
__device__ __forceinline__ float wsum(float v) {
#pragma unroll
    for (int o = 16; o; o >>= 1) v += __shfl_xor_sync(0xFFFFFFFFu, v, o);
    return v;
}
__device__ __forceinline__ uint32_t smem_u32(const void* p) {
    uint32_t a;
    asm("{ .reg .u64 t; cvta.to.shared.u64 t, %1; cvt.u32.u64 %0, t; }" : "=r"(a) : "l"(p));
    return a;
}
__device__ __forceinline__ float tanha(float x) {
    float y; asm("tanh.approx.f32 %0, %1;" : "=f"(y) : "f"(x)); return y;
}
__device__ __forceinline__ uint32_t pack2(float x, float y, uint32_t& lo) {
    uint32_t h;
    asm("cvt.rn.bf16x2.f32 %0, %1, %2;" : "=r"(h) : "f"(y), "f"(x));
    float hx = __uint_as_float(h << 16);
    float hy = __uint_as_float(h & 0xFFFF0000u);
    float rx = x - hx, ry = y - hy;
    asm("cvt.rn.bf16x2.f32 %0, %1, %2;" : "=r"(lo) : "f"(ry), "f"(rx));
    return h;
}
__device__ __forceinline__ void ldsm4(uint32_t (&r)[4], uint32_t addr) {
    asm volatile("ldmatrix.sync.aligned.m8n8.x4.shared.b16 {%0,%1,%2,%3}, [%4];"
                 : "=r"(r[0]), "=r"(r[1]), "=r"(r[2]), "=r"(r[3]) : "r"(addr));
}
__device__ __forceinline__ void mma_bf16(float (&d)[4], const uint32_t (&a)[4],
                                         uint32_t b0, uint32_t b1) {
    asm volatile("mma.sync.aligned.m16n8k16.row.col.f32.bf16.bf16.f32 "
                 "{%0,%1,%2,%3}, {%4,%5,%6,%7}, {%8,%9}, {%0,%1,%2,%3};"
                 : "+f"(d[0]), "+f"(d[1]), "+f"(d[2]), "+f"(d[3])
                 : "r"(a[0]), "r"(a[1]), "r"(a[2]), "r"(a[3]), "r"(b0), "r"(b1));
}
__device__ __forceinline__ uint32_t tile_off(int row, int chunk) {
    return (uint32_t)(row * 256 + (((chunk ^ (row & 7)) & 15) << 4));
}

// ---------------- smem layouts ----------------
#define S_AH 1024
#define S_AL (S_AH + 32768)
#define S_B  (S_AL + 32768)
#define SMEM_G (S_B + 32768)          // 99328 (2 CTA/SM)
#define SA_WH (S_AL + 32768)
#define SA_WL (SA_WH + 16384)
#define SA_WSM (SA_WL + 16384)
#define SMEM_A (SA_WSM + 2048)       // 101376

// A tile conversion: 128 rows x 128 fp32 -> hi/lo bf16 swizzled
__device__ __forceinline__ void convA128(char* sm, const float* __restrict__ src,
                                         int bm, int tid) {
    int r = tid >> 1, half = tid & 1;
    int gr = bm + r;
    bool valid = gr < NN;
    const float4* s4 = (const float4*)(src + (size_t)(valid ? gr : 0) * CC + half * 64);
#pragma unroll
    for (int i = 0; i < 8; ++i) {
        float4 v0 = make_float4(0.f, 0.f, 0.f, 0.f), v1 = v0;
        if (valid) { v0 = s4[2 * i]; v1 = s4[2 * i + 1]; }
        uint4 H, L;
        H.x = pack2(v0.x, v0.y, L.x);
        H.y = pack2(v0.z, v0.w, L.y);
        H.z = pack2(v1.x, v1.y, L.z);
        H.w = pack2(v1.z, v1.w, L.w);
        uint32_t off = tile_off(r, half * 8 + i);
        *(uint4*)(sm + S_AH + off) = H;
        *(uint4*)(sm + S_AL + off) = L;
    }
}
__device__ __forceinline__ void copyB32(char* sm, const char* __restrict__ src, int tid) {
    const uint4* s = (const uint4*)src;
    uint4* d = (uint4*)(sm + S_B);
#pragma unroll
    for (int i = 0; i < 8; ++i) d[tid + i * 256] = s[tid + i * 256];
}

// one bf16 term over K=128 for a 32x64 warp tile
__device__ __forceinline__ void warp_term32(uint32_t aBase, uint32_t bBase,
                                            int wm, int wn, int lane, float (&acc)[16][4]) {
    int quad = lane >> 3, l7 = lane & 7;
    uint32_t arb[2]; int ar7[2];
    int acoff = quad >> 1;
#pragma unroll
    for (int mt = 0; mt < 2; ++mt) {
        int row = wm + mt * 16 + (quad & 1) * 8 + l7;
        arb[mt] = (uint32_t)(row * 256); ar7[mt] = row & 7;
    }
    uint32_t brb[4]; int br7[4];
    int bcoff = quad & 1;
#pragma unroll
    for (int j = 0; j < 4; ++j) {
        int row = wn + j * 16 + (quad >> 1) * 8 + l7;
        brb[j] = (uint32_t)(row * 256); br7[j] = row & 7;
    }
#pragma unroll
    for (int ks = 0; ks < 8; ++ks) {
        uint32_t a[2][4];
#pragma unroll
        for (int mt = 0; mt < 2; ++mt)
            ldsm4(a[mt], aBase + arb[mt] + ((((2 * ks + acoff) ^ ar7[mt]) & 15) << 4));
        uint32_t b[4][4];
#pragma unroll
        for (int j = 0; j < 4; ++j)
            ldsm4(b[j], bBase + brb[j] + ((((2 * ks + bcoff) ^ br7[j]) & 15) << 4));
#pragma unroll
        for (int mt = 0; mt < 2; ++mt)
#pragma unroll
            for (int nt = 0; nt < 8; ++nt)
                mma_bf16(acc[mt * 8 + nt], a[mt],
                         b[nt >> 1][(nt & 1) * 2], b[nt >> 1][(nt & 1) * 2 + 1]);
    }
}
// one bf16 term for a 16x64 warp tile (attention)
__device__ __forceinline__ void warp_term16(uint32_t aBase, uint32_t bBase,
                                            int wm, int lane, float (&acc)[8][4]) {
    int quad = lane >> 3, l7 = lane & 7;
    int arow = wm + (quad & 1) * 8 + l7;
    uint32_t arb = (uint32_t)(arow * 256); int ar7 = arow & 7;
    int acoff = quad >> 1;
    uint32_t brb[4]; int br7[4];
    int bcoff = quad & 1;
#pragma unroll
    for (int j = 0; j < 4; ++j) {
        int row = j * 16 + (quad >> 1) * 8 + l7;
        brb[j] = (uint32_t)(row * 256); br7[j] = row & 7;
    }
#pragma unroll
    for (int ks = 0; ks < 8; ++ks) {
        uint32_t a[4];
        ldsm4(a, aBase + arb + ((((2 * ks + acoff) ^ ar7) & 15) << 4));
        uint32_t b[4][4];
#pragma unroll
        for (int j = 0; j < 4; ++j)
            ldsm4(b[j], bBase + brb[j] + ((((2 * ks + bcoff) ^ br7[j]) & 15) << 4));
#pragma unroll
        for (int nt = 0; nt < 8; ++nt)
            mma_bf16(acc[nt], a, b[nt >> 1][(nt & 1) * 2], b[nt >> 1][(nt & 1) * 2 + 1]);
    }
}

// ---------------- weight pre-conversion (grid (5,4)) ----------------
__global__ void convw_k(const float* W0, const float* W1, const float* W2,
                        const float* W3, const float* W4) {
    const float* W; int N;
    switch (blockIdx.x) {
        case 0: W = W0; N = 128; break;
        case 1: W = W1; N = 128; break;
        case 2: W = W2; N = 128; break;
        case 3: W = W3; N = 128; break;
        default: W = W4; N = 64; break;
    }
    int tid = threadIdx.x;
    int n = tid >> 1, half = tid & 1;
    if (n >= N) return;
    char* dh = g_wt[blockIdx.x][0];
    char* dl = g_wt[blockIdx.x][1];
    int i0 = blockIdx.y * 2;
#pragma unroll
    for (int i = i0; i < i0 + 2; ++i) {
        int k = (half * 8 + i) * 8;
        float v[8];
#pragma unroll
        for (int j = 0; j < 8; ++j) v[j] = __ldg(W + (size_t)(k + j) * N + n);
        uint4 H, L;
        H.x = pack2(v[0], v[1], L.x);
        H.y = pack2(v[2], v[3], L.y);
        H.z = pack2(v[4], v[5], L.z);
        H.w = pack2(v[6], v[7], L.w);
        uint32_t off = tile_off(n, half * 8 + i);
        *(uint4*)(dh + off) = H;
        *(uint4*)(dl + off) = L;
    }
}

// ---------------- CSR build ----------------
__global__ void hist_k(const int* __restrict__ row) {
    int e = blockIdx.x * 256 + threadIdx.x;
    if (e < EE) atomicAdd(&g_cnt[__ldg(row + e)], 1);
}
__global__ void scan_k() {
    __shared__ int ssm[1024];
    int t = threadIdx.x;
    const int CH = (NN + 1023) / 1024;
    int st = t * CH, en = min(st + CH, NN);
    int s = 0;
    for (int i = st; i < en; ++i) s += g_cnt[i];
    ssm[t] = s;
    __syncthreads();
    for (int o = 1; o < 1024; o <<= 1) {
        int v = (t >= o) ? ssm[t - o] : 0;
        __syncthreads();
        ssm[t] += v;
        __syncthreads();
    }
    int run = ssm[t] - s;
    for (int i = st; i < en; ++i) {
        int c = g_cnt[i];
        g_ptr[i] = run;
        g_cnt[i] = run;  // write cursor
        run += c;
    }
    if (t == 0) g_ptr[NN] = EE;
}
__global__ void fill_k(const int* __restrict__ row, const int* __restrict__ col) {
    int e = blockIdx.x * 256 + threadIdx.x;
    if (e < EE) {
        int r = __ldg(row + e);
        int p = atomicAdd(&g_cnt[r], 1);
        g_adj[p] = __ldg(col + e);
    }
}

// ---------------- per-node norm2/sum ----------------
__global__ void __launch_bounds__(256) pre_k(const float* __restrict__ X,
                                             float* __restrict__ n2, float* __restrict__ s1) {
    int node = blockIdx.x * 8 + (threadIdx.x >> 5);
    if (node >= NN) return;
    int lane = threadIdx.x & 31;
    float4 v = *(const float4*)(X + (size_t)node * CC + lane * 4);
    float n = wsum(v.x * v.x + v.y * v.y + v.z * v.z + v.w * v.w);
    float s = wsum(v.x + v.y + v.z + v.w);
    if (lane == 0) { n2[node] = n; s1[node] = s; }
}
__global__ void __launch_bounds__(256) pre2_k(const float* __restrict__ X3,
                                              const float* __restrict__ X4) {
    int node = blockIdx.x * 8 + (threadIdx.x >> 5);
    if (node >= NN) return;
    int lane = threadIdx.x & 31;
    float4 a = *(const float4*)(X3 + (size_t)node * CC + lane * 4);
    float4 b = *(const float4*)(X4 + (size_t)node * CC + lane * 4);
    float n3 = a.x * a.x + a.y * a.y + a.z * a.z + a.w * a.w;
    float n4 = b.x * b.x + b.y * b.y + b.z * b.z + b.w * b.w;
    float s4 = b.x + b.y + b.z + b.w;
#pragma unroll
    for (int o = 16; o; o >>= 1) {
        n3 += __shfl_xor_sync(0xFFFFFFFFu, n3, o);
        n4 += __shfl_xor_sync(0xFFFFFFFFu, n4, o);
        s4 += __shfl_xor_sync(0xFFFFFFFFu, s4, o);
    }
    if (lane == 0) { g_n2a[node] = n3; g_n2b[node] = n4; g_s1b[node] = s4; }
}

// ---------------- layer-0 gather aggregation (cos + eud over x), ILP-2 --------------
__global__ void __launch_bounds__(256) agg1_k(const float* __restrict__ x) {
    int node = blockIdx.x * 8 + (threadIdx.x >> 5);
    if (node >= NN) return;
    int lane = threadIdx.x & 31;
    size_t mo = (size_t)node * CC + lane * 4;
    float4 a = *(const float4*)(x + mo);
    float na = __ldg(g_n2a + node), sa = __ldg(g_s1a + node);
    int st = g_ptr[node], en = g_ptr[node + 1];
    float4 cc = make_float4(0.f, 0.f, 0.f, 0.f), ce = cc;
    int e = st;
    for (; e + 1 < en; e += 2) {
        int j0 = __ldg(g_adj + e), j1 = __ldg(g_adj + e + 1);
        float4 b0 = *(const float4*)(x + (size_t)j0 * CC + lane * 4);
        float4 b1 = *(const float4*)(x + (size_t)j1 * CC + lane * 4);
        float d0 = a.x * b0.x + a.y * b0.y + a.z * b0.z + a.w * b0.w;
        float d1 = a.x * b1.x + a.y * b1.y + a.z * b1.z + a.w * b1.w;
#pragma unroll
        for (int o = 16; o; o >>= 1) {
            d0 += __shfl_xor_sync(0xFFFFFFFFu, d0, o);
            d1 += __shfl_xor_sync(0xFFFFFFFFu, d1, o);
        }
        float nb0 = __ldg(g_n2a + j0), sb0 = __ldg(g_s1a + j0);
        float nb1 = __ldg(g_n2a + j1), sb1 = __ldg(g_s1a + j1);
        float c0 = d0 / fmaxf(sqrtf(na * nb0), 1e-8f);
        float c1 = d1 / fmaxf(sqrtf(na * nb1), 1e-8f);
        float t0 = na + nb0 - 2.f * d0 + 2e-6f * (sa - sb0) + 1.28e-10f;
        float t1 = na + nb1 - 2.f * d1 + 2e-6f * (sa - sb1) + 1.28e-10f;
        float u0 = sqrtf(fmaxf(t0, 0.f)), u1 = sqrtf(fmaxf(t1, 0.f));
        cc.x += c0 * b0.x + c1 * b1.x; cc.y += c0 * b0.y + c1 * b1.y;
        cc.z += c0 * b0.z + c1 * b1.z; cc.w += c0 * b0.w + c1 * b1.w;
        ce.x += u0 * b0.x + u1 * b1.x; ce.y += u0 * b0.y + u1 * b1.y;
        ce.z += u0 * b0.z + u1 * b1.z; ce.w += u0 * b0.w + u1 * b1.w;
    }
    if (e < en) {
        int j0 = __ldg(g_adj + e);
        float4 b0 = *(const float4*)(x + (size_t)j0 * CC + lane * 4);
        float d0 = wsum(a.x * b0.x + a.y * b0.y + a.z * b0.z + a.w * b0.w);
        float nb0 = __ldg(g_n2a + j0), sb0 = __ldg(g_s1a + j0);
        float c0 = d0 / fmaxf(sqrtf(na * nb0), 1e-8f);
        float t0 = na + nb0 - 2.f * d0 + 2e-6f * (sa - sb0) + 1.28e-10f;
        float u0 = sqrtf(fmaxf(t0, 0.f));
        cc.x += c0 * b0.x; cc.y += c0 * b0.y; cc.z += c0 * b0.z; cc.w += c0 * b0.w;
        ce.x += u0 * b0.x; ce.y += u0 * b0.y; ce.z += u0 * b0.z; ce.w += u0 * b0.w;
    }
    float inv = 1.f / fmaxf((float)(en - st), 1.f);
    cc.x *= inv; cc.y *= inv; cc.z *= inv; cc.w *= inv;
    ce.x *= inv; ce.y *= inv; ce.z *= inv; ce.w *= inv;
    *(float4*)(g_aggc + mo) = cc;
    *(float4*)(g_agge + mo) = ce;
}

// ---------------- layer-1 gather aggregation (cos over x3, eud over x4), ILP-2 -------
__global__ void __launch_bounds__(256) agg2_k(const float* __restrict__ x3,
                                              const float* __restrict__ x4) {
    int node = blockIdx.x * 8 + (threadIdx.x >> 5);
    if (node >= NN) return;
    int lane = threadIdx.x & 31;
    size_t mo = (size_t)node * CC + lane * 4;
    float4 a3 = *(const float4*)(x3 + mo);
    float4 a4 = *(const float4*)(x4 + mo);
    float n3 = __ldg(g_n2a + node);
    float n4 = __ldg(g_n2b + node), s4 = __ldg(g_s1b + node);
    int st = g_ptr[node], en = g_ptr[node + 1];
    float4 cc = make_float4(0.f, 0.f, 0.f, 0.f), ce = cc;
    int e = st;
    for (; e + 1 < en; e += 2) {
        int j0 = __ldg(g_adj + e), j1 = __ldg(g_adj + e + 1);
        size_t o0 = (size_t)j0 * CC + lane * 4, o1 = (size_t)j1 * CC + lane * 4;
        float4 b30 = *(const float4*)(x3 + o0);
        float4 b31 = *(const float4*)(x3 + o1);
        float4 b40 = *(const float4*)(x4 + o0);
        float4 b41 = *(const float4*)(x4 + o1);
        float d30 = a3.x * b30.x + a3.y * b30.y + a3.z * b30.z + a3.w * b30.w;
        float d31 = a3.x * b31.x + a3.y * b31.y + a3.z * b31.z + a3.w * b31.w;
        float d40 = a4.x * b40.x + a4.y * b40.y + a4.z * b40.z + a4.w * b40.w;
        float d41 = a4.x * b41.x + a4.y * b41.y + a4.z * b41.z + a4.w * b41.w;
#pragma unroll
        for (int o = 16; o; o >>= 1) {
            d30 += __shfl_xor_sync(0xFFFFFFFFu, d30, o);
            d31 += __shfl_xor_sync(0xFFFFFFFFu, d31, o);
            d40 += __shfl_xor_sync(0xFFFFFFFFu, d40, o);
            d41 += __shfl_xor_sync(0xFFFFFFFFu, d41, o);
        }
        float nb30 = __ldg(g_n2a + j0), nb31 = __ldg(g_n2a + j1);
        float nb40 = __ldg(g_n2b + j0), nb41 = __ldg(g_n2b + j1);
        float sb40 = __ldg(g_s1b + j0), sb41 = __ldg(g_s1b + j1);
        float c0 = d30 / fmaxf(sqrtf(n3 * nb30), 1e-8f);
        float c1 = d31 / fmaxf(sqrtf(n3 * nb31), 1e-8f);
        float t0 = n4 + nb40 - 2.f * d40 + 2e-6f * (s4 - sb40) + 1.28e-10f;
        float t1 = n4 + nb41 - 2.f * d41 + 2e-6f * (s4 - sb41) + 1.28e-10f;
        float u0 = sqrtf(fmaxf(t0, 0.f)), u1 = sqrtf(fmaxf(t1, 0.f));
        cc.x += c0 * b30.x + c1 * b31.x; cc.y += c0 * b30.y + c1 * b31.y;
        cc.z += c0 * b30.z + c1 * b31.z; cc.w += c0 * b30.w + c1 * b31.w;
        ce.x += u0 * b40.x + u1 * b41.x; ce.y += u0 * b40.y + u1 * b41.y;
        ce.z += u0 * b40.z + u1 * b41.z; ce.w += u0 * b40.w + u1 * b41.w;
    }
    if (e < en) {
        int j0 = __ldg(g_adj + e);
        size_t o0 = (size_t)j0 * CC + lane * 4;
        float4 b30 = *(const float4*)(x3 + o0);
        float4 b40 = *(const float4*)(x4 + o0);
        float d30 = a3.x * b30.x + a3.y * b30.y + a3.z * b30.z + a3.w * b30.w;
        float d40 = a4.x * b40.x + a4.y * b40.y + a4.z * b40.z + a4.w * b40.w;
#pragma unroll
        for (int o = 16; o; o >>= 1) {
            d30 += __shfl_xor_sync(0xFFFFFFFFu, d30, o);
            d40 += __shfl_xor_sync(0xFFFFFFFFu, d40, o);
        }
        float nb30 = __ldg(g_n2a + j0);
        float nb40 = __ldg(g_n2b + j0), sb40 = __ldg(g_s1b + j0);
        float c0 = d30 / fmaxf(sqrtf(n3 * nb30), 1e-8f);
        float t0 = n4 + nb40 - 2.f * d40 + 2e-6f * (s4 - sb40) + 1.28e-10f;
        float u0 = sqrtf(fmaxf(t0, 0.f));
        cc.x += c0 * b30.x; cc.y += c0 * b30.y; cc.z += c0 * b30.z; cc.w += c0 * b30.w;
        ce.x += u0 * b40.x; ce.y += u0 * b40.y; ce.z += u0 * b40.z; ce.w += u0 * b40.w;
    }
    float inv = 1.f / fmaxf((float)(en - st), 1.f);
    cc.x *= inv; cc.y *= inv; cc.z *= inv; cc.w *= inv;
    ce.x *= inv; ce.y *= inv; ce.z *= inv; ce.w *= inv;
    *(float4*)(g_aggc + mo) = cc;
    *(float4*)(g_agge + mo) = ce;
}

// ---------------- gemm_one: O = A@W + bias ----------------
__global__ void __launch_bounds__(256, 2) gemm_one(
    const float* __restrict__ A, int w, const float* __restrict__ bias,
    float* __restrict__ O)
{
    extern __shared__ char sm[];
    int tid = threadIdx.x, lane = tid & 31, wid = tid >> 5;
    int bm = blockIdx.x * 128;
    uint32_t smb = smem_u32(sm);
    float* sbias = (float*)sm;
    if (tid < 128) sbias[tid] = bias[tid];

    float acc[16][4];
#pragma unroll
    for (int i = 0; i < 16; ++i)
#pragma unroll
        for (int j = 0; j < 4; ++j) acc[i][j] = 0.f;

    const int wm = (wid & 3) * 32, wn = (wid >> 2) * 64;

    convA128(sm, A, bm, tid);
    copyB32(sm, g_wt[w][0], tid);
    __syncthreads();
    warp_term32(smb + S_AH, smb + S_B, wm, wn, lane, acc);
    warp_term32(smb + S_AL, smb + S_B, wm, wn, lane, acc);
    __syncthreads();
    copyB32(sm, g_wt[w][1], tid);
    __syncthreads();
    warp_term32(smb + S_AH, smb + S_B, wm, wn, lane, acc);

    int g = lane >> 2, tg = lane & 3;
#pragma unroll
    for (int mt = 0; mt < 2; ++mt) {
        int m0 = bm + wm + mt * 16 + g;
#pragma unroll
        for (int nt = 0; nt < 8; ++nt) {
            int cl = wn + nt * 8 + tg * 2;
            float b0 = sbias[cl], b1 = sbias[cl + 1];
            int idx = mt * 8 + nt;
            if (m0 < NN) {
                float2 v;
                v.x = acc[idx][0] + b0; v.y = acc[idx][1] + b1;
                *(float2*)(O + (size_t)m0 * CC + cl) = v;
            }
            if (m0 + 8 < NN) {
                float2 v;
                v.x = acc[idx][2] + b0; v.y = acc[idx][3] + b1;
                *(float2*)(O + (size_t)(m0 + 8) * CC + cl) = v;
            }
        }
    }
}

// ---------------- gemm_cadd: O[br] = relu(agg[br] @ W + Cadd) ----------------
__global__ void __launch_bounds__(256, 2) gemm_cadd(
    int w, const float* __restrict__ Cadd,
    float* __restrict__ Oc, float* __restrict__ Oe)
{
    extern __shared__ char sm[];
    int tid = threadIdx.x, lane = tid & 31, wid = tid >> 5;
    int bm = blockIdx.x * 128, br = blockIdx.y;
    uint32_t smb = smem_u32(sm);
    const float* A = br ? g_agge : g_aggc;
    float* O = br ? Oe : Oc;

    float acc[16][4];
#pragma unroll
    for (int i = 0; i < 16; ++i)
#pragma unroll
        for (int j = 0; j < 4; ++j) acc[i][j] = 0.f;

    const int wm = (wid & 3) * 32, wn = (wid >> 2) * 64;

    convA128(sm, A, bm, tid);
    copyB32(sm, g_wt[w][0], tid);
    __syncthreads();
    warp_term32(smb + S_AH, smb + S_B, wm, wn, lane, acc);
    warp_term32(smb + S_AL, smb + S_B, wm, wn, lane, acc);
    __syncthreads();
    copyB32(sm, g_wt[w][1], tid);
    __syncthreads();
    warp_term32(smb + S_AH, smb + S_B, wm, wn, lane, acc);

    int g = lane >> 2, tg = lane & 3;
#pragma unroll
    for (int mt = 0; mt < 2; ++mt) {
        int m0 = bm + wm + mt * 16 + g;
#pragma unroll
        for (int nt = 0; nt < 8; ++nt) {
            int cl = wn + nt * 8 + tg * 2;
            int idx = mt * 8 + nt;
            if (m0 < NN) {
                float2 cv = *(const float2*)(Cadd + (size_t)m0 * CC + cl);
                float2 v;
                v.x = fmaxf(acc[idx][0] + cv.x, 0.f);
                v.y = fmaxf(acc[idx][1] + cv.y, 0.f);
                *(float2*)(O + (size_t)m0 * CC + cl) = v;
            }
            if (m0 + 8 < NN) {
                float2 cv = *(const float2*)(Cadd + (size_t)(m0 + 8) * CC + cl);
                float2 v;
                v.x = fmaxf(acc[idx][2] + cv.x, 0.f);
                v.y = fmaxf(acc[idx][3] + cv.y, 0.f);
                *(float2*)(O + (size_t)(m0 + 8) * CC + cl) = v;
            }
        }
    }
}

// ---------------- L1 fused GEMM: O[br] = A1@W1 + agg[br]@W2 + bias ----------------
__global__ void __launch_bounds__(256, 2) gemm_two(
    const float* __restrict__ A1c, const float* __restrict__ A1e,
    int w1, int w2, const float* __restrict__ bias,
    float* __restrict__ Oc, float* __restrict__ Oe)
{
    extern __shared__ char sm[];
    int tid = threadIdx.x, lane = tid & 31, wid = tid >> 5;
    int bm = blockIdx.x * 128, br = blockIdx.y;
    uint32_t smb = smem_u32(sm);
    float* sbias = (float*)sm;
    if (tid < 128) sbias[tid] = bias[tid];
    const float* A1 = br ? A1e : A1c;
    const float* A2 = br ? g_agge : g_aggc;
    float* O = br ? Oe : Oc;

    float acc[16][4];
#pragma unroll
    for (int i = 0; i < 16; ++i)
#pragma unroll
        for (int j = 0; j < 4; ++j) acc[i][j] = 0.f;

    const int wm = (wid & 3) * 32, wn = (wid >> 2) * 64;

    for (int pass = 0; pass < 2; ++pass) {
        const float* A = pass ? A2 : A1;
        int w = pass ? w2 : w1;
        convA128(sm, A, bm, tid);
        copyB32(sm, g_wt[w][0], tid);
        __syncthreads();
        warp_term32(smb + S_AH, smb + S_B, wm, wn, lane, acc);
        warp_term32(smb + S_AL, smb + S_B, wm, wn, lane, acc);
        __syncthreads();
        copyB32(sm, g_wt[w][1], tid);
        __syncthreads();
        warp_term32(smb + S_AH, smb + S_B, wm, wn, lane, acc);
        __syncthreads();
    }

    int g = lane >> 2, tg = lane & 3;
#pragma unroll
    for (int mt = 0; mt < 2; ++mt) {
        int m0 = bm + wm + mt * 16 + g;
#pragma unroll
        for (int nt = 0; nt < 8; ++nt) {
            int cl = wn + nt * 8 + tg * 2;
            float b0 = sbias[cl], b1 = sbias[cl + 1];
            int idx = mt * 8 + nt;
            if (m0 < NN) {
                float2 v;
                v.x = acc[idx][0] + b0; v.y = acc[idx][1] + b1;
                *(float2*)(O + (size_t)m0 * CC + cl) = v;
            }
            if (m0 + 8 < NN) {
                float2 v;
                v.x = acc[idx][2] + b0; v.y = acc[idx][3] + b1;
                *(float2*)(O + (size_t)(m0 + 8) * CC + cl) = v;
            }
        }
    }
}

// ---------------- attention: tensor-core logits + softmax blend ----------------
__global__ void __launch_bounds__(256) att_tc(
    const float* __restrict__ x1, const float* __restrict__ x2,
    const float* __restrict__ x3, const float* __restrict__ x4,
    const float* __restrict__ ab1, const float* __restrict__ aW2,
    float* __restrict__ emb)
{
    extern __shared__ char sm[];
    int tid = threadIdx.x, lane = tid & 31, wid = tid >> 5;
    int bm = blockIdx.x * 128;
    uint32_t smb = smem_u32(sm);
    float* b1s = (float*)sm;
    float* w2s = (float*)(sm + 256);
    float* wsm = (float*)(sm + SA_WSM);
    if (tid < 64) { b1s[tid] = ab1[tid]; w2s[tid] = aW2[tid]; }
    {
        const uint4* sh = (const uint4*)g_wt[4][0];
        const uint4* sl = (const uint4*)g_wt[4][1];
        uint4* dh = (uint4*)(sm + SA_WH);
        uint4* dl = (uint4*)(sm + SA_WL);
#pragma unroll
        for (int i = 0; i < 4; ++i) {
            dh[tid + i * 256] = sh[tid + i * 256];
            dl[tid + i * 256] = sl[tid + i * 256];
        }
    }
    const float* Xb[4] = {x1, x2, x3, x4};
    int wm = wid * 16;
    int g = lane >> 2, tg = lane & 3;
    for (int b = 0; b < 4; ++b) {
        __syncthreads();
        convA128(sm, Xb[b], bm, tid);
        __syncthreads();
        float acc[8][4];
#pragma unroll
        for (int i = 0; i < 8; ++i)
#pragma unroll
            for (int j = 0; j < 4; ++j) acc[i][j] = 0.f;
        warp_term16(smb + S_AH, smb + SA_WH, wm, lane, acc);
        warp_term16(smb + S_AH, smb + SA_WL, wm, lane, acc);
        warp_term16(smb + S_AL, smb + SA_WH, wm, lane, acc);
        float w0 = 0.f, w1p = 0.f;
#pragma unroll
        for (int nt = 0; nt < 8; ++nt) {
            int cl = nt * 8 + tg * 2;
            w0  += tanha(acc[nt][0] + b1s[cl]) * w2s[cl]
                 + tanha(acc[nt][1] + b1s[cl + 1]) * w2s[cl + 1];
            w1p += tanha(acc[nt][2] + b1s[cl]) * w2s[cl]
                 + tanha(acc[nt][3] + b1s[cl + 1]) * w2s[cl + 1];
        }
        w0 += __shfl_xor_sync(0xFFFFFFFFu, w0, 1);
        w0 += __shfl_xor_sync(0xFFFFFFFFu, w0, 2);
        w1p += __shfl_xor_sync(0xFFFFFFFFu, w1p, 1);
        w1p += __shfl_xor_sync(0xFFFFFFFFu, w1p, 2);
        if (tg == 0) {
            wsm[(wm + g) * 4 + b] = w0;
            wsm[(wm + 8 + g) * 4 + b] = w1p;
        }
    }
    __syncthreads();
    int row = tid >> 1, half = tid & 1;
    int gr = bm + row;
    if (gr >= NN) return;
    float l0 = wsm[row * 4 + 0], l1 = wsm[row * 4 + 1];
    float l2 = wsm[row * 4 + 2], l3 = wsm[row * 4 + 3];
    float m = fmaxf(fmaxf(l0, l1), fmaxf(l2, l3));
    float e0 = __expf(l0 - m), e1 = __expf(l1 - m), e2 = __expf(l2 - m), e3 = __expf(l3 - m);
    float inv = 1.f / (e0 + e1 + e2 + e3);
    float be0 = e0 * inv, be1 = e1 * inv, be2 = e2 * inv, be3 = e3 * inv;
    size_t base = (size_t)gr * CC + half * 64;
#pragma unroll
    for (int c = 0; c < 16; ++c) {
        float4 z0 = *(const float4*)(x1 + base + c * 4);
        float4 z1 = *(const float4*)(x2 + base + c * 4);
        float4 z2 = *(const float4*)(x3 + base + c * 4);
        float4 z3 = *(const float4*)(x4 + base + c * 4);
        float4 o;
        o.x = be0 * z0.x + be1 * z1.x + be2 * z2.x + be3 * z3.x;
        o.y = be0 * z0.y + be1 * z1.y + be2 * z2.y + be3 * z3.y;
        o.z = be0 * z0.z + be1 * z1.z + be2 * z2.z + be3 * z3.z;
        o.w = be0 * z0.w + be1 * z1.w + be2 * z2.w + be3 * z3.w;
        *(float4*)(emb + base + c * 4) = o;
    }
}

// ---------------- launch ----------------
extern "C" void kernel_launch(void* const* d_in, const int* in_sizes, int n_in,
                              void* d_out, int out_size)
{
    const float* x   = (const float*)d_in[0];
    const int*   row = (const int*)d_in[1];
    const int*   col = (const int*)d_in[2];
    const float* Wl0 = (const float*)d_in[3];
    const float* bl0 = (const float*)d_in[4];
    const float* Wr0 = (const float*)d_in[5];
    const float* Wl1 = (const float*)d_in[6];
    const float* bl1 = (const float*)d_in[7];
    const float* Wr1 = (const float*)d_in[8];
    const float* aW1 = (const float*)d_in[9];
    const float* ab1 = (const float*)d_in[10];
    const float* aW2 = (const float*)d_in[11];

    float* out = (float*)d_out;
    float* x3  = out + (size_t)NN * CC;
    float* x4  = out + 2 * (size_t)NN * CC;

    float *x1, *x2, *n2a, *s1a;
    int* cnt;
    cudaGetSymbolAddress((void**)&x1,  g_x1);
    cudaGetSymbolAddress((void**)&x2,  g_x2);
    cudaGetSymbolAddress((void**)&n2a, g_n2a);
    cudaGetSymbolAddress((void**)&s1a, g_s1a);
    cudaGetSymbolAddress((void**)&cnt, g_cnt);

    cudaFuncSetAttribute(gemm_one,  cudaFuncAttributeMaxDynamicSharedMemorySize, SMEM_G);
    cudaFuncSetAttribute(gemm_cadd, cudaFuncAttributeMaxDynamicSharedMemorySize, SMEM_G);
    cudaFuncSetAttribute(gemm_two,  cudaFuncAttributeMaxDynamicSharedMemorySize, SMEM_G);
    cudaFuncSetAttribute(att_tc,    cudaFuncAttributeMaxDynamicSharedMemorySize, SMEM_A);

    const int gE = (EE + 255) / 256;       // 3125
    const int gN = (NN + 7) / 8;           // 6250
    const int gG = (NN + 127) / 128;       // 391
    const dim3 gG2(gG, 2);

    // CSR (row layer-invariant -> built once, reused by both layers)
    cudaMemsetAsync(cnt, 0, NN * sizeof(int));
    hist_k<<<gE, 256>>>(row);
    scan_k<<<1, 1024>>>();
    fill_k<<<gE, 256>>>(row, col);

    // weights -> bf16 hi/lo tiles
    convw_k<<<dim3(5, 4), 256>>>(Wr0, Wl0, Wr1, Wl1, aW1);

    // layer 0
    pre_k<<<gN, 256>>>(x, n2a, s1a);
    gemm_one<<<gG, 256, SMEM_G>>>(x, 0, bl0, x1);              // xwr = x@Wr0 + bl0
    agg1_k<<<gN, 256>>>(x);                                    // deg-normalized gather
    gemm_cadd<<<gG2, 256, SMEM_G>>>(1, x1, x3, x4);            // relu(agg@Wl0 + xwr)

    // layer 1
    pre2_k<<<gN, 256>>>(x3, x4);
    agg2_k<<<gN, 256>>>(x3, x4);
    gemm_two<<<gG2, 256, SMEM_G>>>(x3, x4, 2, 3, bl1, x1, x2); // x1/x2 outputs

    // attention
    att_tc<<<gG, 256, SMEM_A>>>(x1, x2, x3, x4, ab1, aW2, out);
}

// round 13
// speedup vs baseline: 1.8043x; 1.0856x over previous
#include <cuda_runtime.h>
#include <cuda_bf16.h>
#include <cstdint>
#include <cstddef>

#define NN 50000
#define EE 800000
#define CC 128

// ---------------- device globals ----------------
__device__ float g_aggc[NN * CC];
__device__ float g_agge[NN * CC];
__device__ float g_x1[NN * CC];     // L0: xwr scratch ; L1: x1 output
__device__ float g_x2[NN * CC];
__device__ float g_n2a[NN], g_s1a[NN], g_n2b[NN], g_s1b[NN];
__device__ int   g_ptr[NN + 1];
__device__ int   g_cnt[NN];
__device__ int   g_adj[EE];
__device__ __align__(16) char g_wt[5][2][32768];  // 0=Wr0 1=Wl0 2=Wr1 3=Wl1 4=attW1

// ---------------- helpers ----------------
__device__ __forceinline__ float wsum(float v) {
#pragma unroll
    for (int o = 16; o; o >>= 1) v += __shfl_xor_sync(0xFFFFFFFFu, v, o);
    return v;
}
__device__ __forceinline__ uint32_t smem_u32(const void* p) {
    uint32_t a;
    asm("{ .reg .u64 t; cvta.to.shared.u64 t, %1; cvt.u32.u64 %0, t; }" : "=r"(a) : "l"(p));
    return a;
}
__device__ __forceinline__ float tanha(float x) {
    float y; asm("tanh.approx.f32 %0, %1;" : "=f"(y) : "f"(x)); return y;
}
__device__ __forceinline__ uint32_t pack2(float x, float y, uint32_t& lo) {
    uint32_t h;
    asm("cvt.rn.bf16x2.f32 %0, %1, %2;" : "=r"(h) : "f"(y), "f"(x));
    float hx = __uint_as_float(h << 16);
    float hy = __uint_as_float(h & 0xFFFF0000u);
    float rx = x - hx, ry = y - hy;
    asm("cvt.rn.bf16x2.f32 %0, %1, %2;" : "=r"(lo) : "f"(ry), "f"(rx));
    return h;
}
__device__ __forceinline__ void ldsm4(uint32_t (&r)[4], uint32_t addr) {
    asm volatile("ldmatrix.sync.aligned.m8n8.x4.shared.b16 {%0,%1,%2,%3}, [%4];"
                 : "=r"(r[0]), "=r"(r[1]), "=r"(r[2]), "=r"(r[3]) : "r"(addr));
}
__device__ __forceinline__ void mma_bf16(float (&d)[4], const uint32_t (&a)[4],
                                         uint32_t b0, uint32_t b1) {
    asm volatile("mma.sync.aligned.m16n8k16.row.col.f32.bf16.bf16.f32 "
                 "{%0,%1,%2,%3}, {%4,%5,%6,%7}, {%8,%9}, {%0,%1,%2,%3};"
                 : "+f"(d[0]), "+f"(d[1]), "+f"(d[2]), "+f"(d[3])
                 : "r"(a[0]), "r"(a[1]), "r"(a[2]), "r"(a[3]), "r"(b0), "r"(b1));
}
__device__ __forceinline__ uint32_t tile_off(int row, int chunk) {
    return (uint32_t)(row * 256 + (((chunk ^ (row & 7)) & 15) << 4));
}

// ---------------- smem layouts ----------------
#define S_AH 1024
#define S_AL (S_AH + 32768)
#define S_B  (S_AL + 32768)
#define SMEM_G (S_B + 32768)          // 99328 (2 CTA/SM)
#define SA_WH (S_AL + 32768)
#define SA_WL (SA_WH + 16384)
#define SA_WSM (SA_WL + 16384)
#define SMEM_A (SA_WSM + 2048)       // 101376

// A tile conversion: 128 rows x 128 fp32 -> hi/lo bf16 swizzled
__device__ __forceinline__ void convA128(char* sm, const float* __restrict__ src,
                                         int bm, int tid) {
    int r = tid >> 1, half = tid & 1;
    int gr = bm + r;
    bool valid = gr < NN;
    const float4* s4 = (const float4*)(src + (size_t)(valid ? gr : 0) * CC + half * 64);
#pragma unroll
    for (int i = 0; i < 8; ++i) {
        float4 v0 = make_float4(0.f, 0.f, 0.f, 0.f), v1 = v0;
        if (valid) { v0 = s4[2 * i]; v1 = s4[2 * i + 1]; }
        uint4 H, L;
        H.x = pack2(v0.x, v0.y, L.x);
        H.y = pack2(v0.z, v0.w, L.y);
        H.z = pack2(v1.x, v1.y, L.z);
        H.w = pack2(v1.z, v1.w, L.w);
        uint32_t off = tile_off(r, half * 8 + i);
        *(uint4*)(sm + S_AH + off) = H;
        *(uint4*)(sm + S_AL + off) = L;
    }
}
__device__ __forceinline__ void copyB32(char* sm, const char* __restrict__ src, int tid) {
    const uint4* s = (const uint4*)src;
    uint4* d = (uint4*)(sm + S_B);
#pragma unroll
    for (int i = 0; i < 8; ++i) d[tid + i * 256] = s[tid + i * 256];
}

// ---------------- warp MMA: 32x64 tile ----------------
struct WC32 {
    uint32_t arb[2]; int ar7[2]; int acoff;
    uint32_t brb[4]; int br7[4]; int bcoff;
};
__device__ __forceinline__ void wc32_init(WC32& w, int wm, int wn, int lane) {
    int quad = lane >> 3, l7 = lane & 7;
    w.acoff = quad >> 1;
#pragma unroll
    for (int mt = 0; mt < 2; ++mt) {
        int row = wm + mt * 16 + (quad & 1) * 8 + l7;
        w.arb[mt] = (uint32_t)(row * 256); w.ar7[mt] = row & 7;
    }
    w.bcoff = quad & 1;
#pragma unroll
    for (int j = 0; j < 4; ++j) {
        int row = wn + j * 16 + (quad >> 1) * 8 + l7;
        w.brb[j] = (uint32_t)(row * 256); w.br7[j] = row & 7;
    }
}
// pair: (A_hi + A_lo) against one B — B fragments loaded once per k-step
__device__ __forceinline__ void term_pair32(uint32_t aH, uint32_t aL, uint32_t bBase,
                                            const WC32& w, float (&acc)[16][4]) {
#pragma unroll
    for (int ks = 0; ks < 8; ++ks) {
        uint32_t b[4][4];
#pragma unroll
        for (int j = 0; j < 4; ++j)
            ldsm4(b[j], bBase + w.brb[j] + ((((2 * ks + w.bcoff) ^ w.br7[j]) & 15) << 4));
        uint32_t a[2][4];
#pragma unroll
        for (int mt = 0; mt < 2; ++mt)
            ldsm4(a[mt], aH + w.arb[mt] + ((((2 * ks + w.acoff) ^ w.ar7[mt]) & 15) << 4));
#pragma unroll
        for (int mt = 0; mt < 2; ++mt)
#pragma unroll
            for (int nt = 0; nt < 8; ++nt)
                mma_bf16(acc[mt * 8 + nt], a[mt],
                         b[nt >> 1][(nt & 1) * 2], b[nt >> 1][(nt & 1) * 2 + 1]);
#pragma unroll
        for (int mt = 0; mt < 2; ++mt)
            ldsm4(a[mt], aL + w.arb[mt] + ((((2 * ks + w.acoff) ^ w.ar7[mt]) & 15) << 4));
#pragma unroll
        for (int mt = 0; mt < 2; ++mt)
#pragma unroll
            for (int nt = 0; nt < 8; ++nt)
                mma_bf16(acc[mt * 8 + nt], a[mt],
                         b[nt >> 1][(nt & 1) * 2], b[nt >> 1][(nt & 1) * 2 + 1]);
    }
}
// single A against one B
__device__ __forceinline__ void term_one32(uint32_t aBase, uint32_t bBase,
                                           const WC32& w, float (&acc)[16][4]) {
#pragma unroll
    for (int ks = 0; ks < 8; ++ks) {
        uint32_t b[4][4];
#pragma unroll
        for (int j = 0; j < 4; ++j)
            ldsm4(b[j], bBase + w.brb[j] + ((((2 * ks + w.bcoff) ^ w.br7[j]) & 15) << 4));
        uint32_t a[2][4];
#pragma unroll
        for (int mt = 0; mt < 2; ++mt)
            ldsm4(a[mt], aBase + w.arb[mt] + ((((2 * ks + w.acoff) ^ w.ar7[mt]) & 15) << 4));
#pragma unroll
        for (int mt = 0; mt < 2; ++mt)
#pragma unroll
            for (int nt = 0; nt < 8; ++nt)
                mma_bf16(acc[mt * 8 + nt], a[mt],
                         b[nt >> 1][(nt & 1) * 2], b[nt >> 1][(nt & 1) * 2 + 1]);
    }
}
// full 3-term pass: (aH+aL)@bHi then aH@bLo (bLo copied by caller between)
__device__ __forceinline__ void gemm_pass(char* sm, uint32_t smb, int w,
                                          const WC32& wc, int tid, float (&acc)[16][4]) {
    copyB32(sm, g_wt[w][0], tid);
    __syncthreads();
    term_pair32(smb + S_AH, smb + S_AL, smb + S_B, wc, acc);
    __syncthreads();
    copyB32(sm, g_wt[w][1], tid);
    __syncthreads();
    term_one32(smb + S_AH, smb + S_B, wc, acc);
}

// ---------------- warp MMA: 16x64 tile (attention) ----------------
struct WC16 {
    uint32_t arb; int ar7; int acoff;
    uint32_t brb[4]; int br7[4]; int bcoff;
};
__device__ __forceinline__ void wc16_init(WC16& w, int wm, int lane) {
    int quad = lane >> 3, l7 = lane & 7;
    int arow = wm + (quad & 1) * 8 + l7;
    w.arb = (uint32_t)(arow * 256); w.ar7 = arow & 7;
    w.acoff = quad >> 1;
    w.bcoff = quad & 1;
#pragma unroll
    for (int j = 0; j < 4; ++j) {
        int row = j * 16 + (quad >> 1) * 8 + l7;
        w.brb[j] = (uint32_t)(row * 256); w.br7[j] = row & 7;
    }
}
__device__ __forceinline__ void term_pair16(uint32_t aH, uint32_t aL, uint32_t bBase,
                                            const WC16& w, float (&acc)[8][4]) {
#pragma unroll
    for (int ks = 0; ks < 8; ++ks) {
        uint32_t b[4][4];
#pragma unroll
        for (int j = 0; j < 4; ++j)
            ldsm4(b[j], bBase + w.brb[j] + ((((2 * ks + w.bcoff) ^ w.br7[j]) & 15) << 4));
        uint32_t a[4];
        ldsm4(a, aH + w.arb + ((((2 * ks + w.acoff) ^ w.ar7) & 15) << 4));
#pragma unroll
        for (int nt = 0; nt < 8; ++nt)
            mma_bf16(acc[nt], a, b[nt >> 1][(nt & 1) * 2], b[nt >> 1][(nt & 1) * 2 + 1]);
        ldsm4(a, aL + w.arb + ((((2 * ks + w.acoff) ^ w.ar7) & 15) << 4));
#pragma unroll
        for (int nt = 0; nt < 8; ++nt)
            mma_bf16(acc[nt], a, b[nt >> 1][(nt & 1) * 2], b[nt >> 1][(nt & 1) * 2 + 1]);
    }
}
__device__ __forceinline__ void term_one16(uint32_t aBase, uint32_t bBase,
                                           const WC16& w, float (&acc)[8][4]) {
#pragma unroll
    for (int ks = 0; ks < 8; ++ks) {
        uint32_t b[4][4];
#pragma unroll
        for (int j = 0; j < 4; ++j)
            ldsm4(b[j], bBase + w.brb[j] + ((((2 * ks + w.bcoff) ^ w.br7[j]) & 15) << 4));
        uint32_t a[4];
        ldsm4(a, aBase + w.arb + ((((2 * ks + w.acoff) ^ w.ar7) & 15) << 4));
#pragma unroll
        for (int nt = 0; nt < 8; ++nt)
            mma_bf16(acc[nt], a, b[nt >> 1][(nt & 1) * 2], b[nt >> 1][(nt & 1) * 2 + 1]);
    }
}

// ---------------- weight pre-conversion (grid (5,4)) ----------------
__global__ void convw_k(const float* W0, const float* W1, const float* W2,
                        const float* W3, const float* W4) {
    const float* W; int N;
    switch (blockIdx.x) {
        case 0: W = W0; N = 128; break;
        case 1: W = W1; N = 128; break;
        case 2: W = W2; N = 128; break;
        case 3: W = W3; N = 128; break;
        default: W = W4; N = 64; break;
    }
    int tid = threadIdx.x;
    int n = tid >> 1, half = tid & 1;
    if (n >= N) return;
    char* dh = g_wt[blockIdx.x][0];
    char* dl = g_wt[blockIdx.x][1];
    int i0 = blockIdx.y * 2;
#pragma unroll
    for (int i = i0; i < i0 + 2; ++i) {
        int k = (half * 8 + i) * 8;
        float v[8];
#pragma unroll
        for (int j = 0; j < 8; ++j) v[j] = __ldg(W + (size_t)(k + j) * N + n);
        uint4 H, L;
        H.x = pack2(v[0], v[1], L.x);
        H.y = pack2(v[2], v[3], L.y);
        H.z = pack2(v[4], v[5], L.z);
        H.w = pack2(v[6], v[7], L.w);
        uint32_t off = tile_off(n, half * 8 + i);
        *(uint4*)(dh + off) = H;
        *(uint4*)(dl + off) = L;
    }
}

// ---------------- CSR build ----------------
__global__ void hist_k(const int* __restrict__ row) {
    int e = blockIdx.x * 256 + threadIdx.x;
    if (e < EE) atomicAdd(&g_cnt[__ldg(row + e)], 1);
}
__global__ void scan_k() {
    __shared__ int ssm[1024];
    int t = threadIdx.x;
    const int CH = (NN + 1023) / 1024;
    int st = t * CH, en = min(st + CH, NN);
    int s = 0;
    for (int i = st; i < en; ++i) s += g_cnt[i];
    ssm[t] = s;
    __syncthreads();
    for (int o = 1; o < 1024; o <<= 1) {
        int v = (t >= o) ? ssm[t - o] : 0;
        __syncthreads();
        ssm[t] += v;
        __syncthreads();
    }
    int run = ssm[t] - s;
    for (int i = st; i < en; ++i) {
        int c = g_cnt[i];
        g_ptr[i] = run;
        g_cnt[i] = run;  // write cursor
        run += c;
    }
    if (t == 0) g_ptr[NN] = EE;
}
__global__ void fill_k(const int* __restrict__ row, const int* __restrict__ col) {
    int e = blockIdx.x * 256 + threadIdx.x;
    if (e < EE) {
        int r = __ldg(row + e);
        int p = atomicAdd(&g_cnt[r], 1);
        g_adj[p] = __ldg(col + e);
    }
}

// ---------------- per-node norm2/sum ----------------
__global__ void __launch_bounds__(256) pre_k(const float* __restrict__ X,
                                             float* __restrict__ n2, float* __restrict__ s1) {
    int node = blockIdx.x * 8 + (threadIdx.x >> 5);
    if (node >= NN) return;
    int lane = threadIdx.x & 31;
    float4 v = *(const float4*)(X + (size_t)node * CC + lane * 4);
    float n = wsum(v.x * v.x + v.y * v.y + v.z * v.z + v.w * v.w);
    float s = wsum(v.x + v.y + v.z + v.w);
    if (lane == 0) { n2[node] = n; s1[node] = s; }
}
__global__ void __launch_bounds__(256) pre2_k(const float* __restrict__ X3,
                                              const float* __restrict__ X4) {
    int node = blockIdx.x * 8 + (threadIdx.x >> 5);
    if (node >= NN) return;
    int lane = threadIdx.x & 31;
    float4 a = *(const float4*)(X3 + (size_t)node * CC + lane * 4);
    float4 b = *(const float4*)(X4 + (size_t)node * CC + lane * 4);
    float n3 = a.x * a.x + a.y * a.y + a.z * a.z + a.w * a.w;
    float n4 = b.x * b.x + b.y * b.y + b.z * b.z + b.w * b.w;
    float s4 = b.x + b.y + b.z + b.w;
#pragma unroll
    for (int o = 16; o; o >>= 1) {
        n3 += __shfl_xor_sync(0xFFFFFFFFu, n3, o);
        n4 += __shfl_xor_sync(0xFFFFFFFFu, n4, o);
        s4 += __shfl_xor_sync(0xFFFFFFFFu, s4, o);
    }
    if (lane == 0) { g_n2a[node] = n3; g_n2b[node] = n4; g_s1b[node] = s4; }
}

// ---------------- layer-0 gather aggregation ----------------
__global__ void __launch_bounds__(256) agg1_k(const float* __restrict__ x) {
    int node = blockIdx.x * 8 + (threadIdx.x >> 5);
    if (node >= NN) return;
    int lane = threadIdx.x & 31;
    size_t mo = (size_t)node * CC + lane * 4;
    float4 a = *(const float4*)(x + mo);
    float na = __ldg(g_n2a + node), sa = __ldg(g_s1a + node);
    int st = g_ptr[node], en = g_ptr[node + 1];
    float4 cc = make_float4(0.f, 0.f, 0.f, 0.f), ce = cc;
    int e = st;
    for (; e + 1 < en; e += 2) {
        int j0 = __ldg(g_adj + e), j1 = __ldg(g_adj + e + 1);
        float4 b0 = *(const float4*)(x + (size_t)j0 * CC + lane * 4);
        float4 b1 = *(const float4*)(x + (size_t)j1 * CC + lane * 4);
        float d0 = a.x * b0.x + a.y * b0.y + a.z * b0.z + a.w * b0.w;
        float d1 = a.x * b1.x + a.y * b1.y + a.z * b1.z + a.w * b1.w;
#pragma unroll
        for (int o = 16; o; o >>= 1) {
            d0 += __shfl_xor_sync(0xFFFFFFFFu, d0, o);
            d1 += __shfl_xor_sync(0xFFFFFFFFu, d1, o);
        }
        float nb0 = __ldg(g_n2a + j0), sb0 = __ldg(g_s1a + j0);
        float nb1 = __ldg(g_n2a + j1), sb1 = __ldg(g_s1a + j1);
        float c0 = d0 / fmaxf(sqrtf(na * nb0), 1e-8f);
        float c1 = d1 / fmaxf(sqrtf(na * nb1), 1e-8f);
        float t0 = na + nb0 - 2.f * d0 + 2e-6f * (sa - sb0) + 1.28e-10f;
        float t1 = na + nb1 - 2.f * d1 + 2e-6f * (sa - sb1) + 1.28e-10f;
        float u0 = sqrtf(fmaxf(t0, 0.f)), u1 = sqrtf(fmaxf(t1, 0.f));
        cc.x += c0 * b0.x + c1 * b1.x; cc.y += c0 * b0.y + c1 * b1.y;
        cc.z += c0 * b0.z + c1 * b1.z; cc.w += c0 * b0.w + c1 * b1.w;
        ce.x += u0 * b0.x + u1 * b1.x; ce.y += u0 * b0.y + u1 * b1.y;
        ce.z += u0 * b0.z + u1 * b1.z; ce.w += u0 * b0.w + u1 * b1.w;
    }
    if (e < en) {
        int j0 = __ldg(g_adj + e);
        float4 b0 = *(const float4*)(x + (size_t)j0 * CC + lane * 4);
        float d0 = wsum(a.x * b0.x + a.y * b0.y + a.z * b0.z + a.w * b0.w);
        float nb0 = __ldg(g_n2a + j0), sb0 = __ldg(g_s1a + j0);
        float c0 = d0 / fmaxf(sqrtf(na * nb0), 1e-8f);
        float t0 = na + nb0 - 2.f * d0 + 2e-6f * (sa - sb0) + 1.28e-10f;
        float u0 = sqrtf(fmaxf(t0, 0.f));
        cc.x += c0 * b0.x; cc.y += c0 * b0.y; cc.z += c0 * b0.z; cc.w += c0 * b0.w;
        ce.x += u0 * b0.x; ce.y += u0 * b0.y; ce.z += u0 * b0.z; ce.w += u0 * b0.w;
    }
    float inv = 1.f / fmaxf((float)(en - st), 1.f);
    cc.x *= inv; cc.y *= inv; cc.z *= inv; cc.w *= inv;
    ce.x *= inv; ce.y *= inv; ce.z *= inv; ce.w *= inv;
    *(float4*)(g_aggc + mo) = cc;
    *(float4*)(g_agge + mo) = ce;
}

// ---------------- layer-1 gather aggregation ----------------
__global__ void __launch_bounds__(256) agg2_k(const float* __restrict__ x3,
                                              const float* __restrict__ x4) {
    int node = blockIdx.x * 8 + (threadIdx.x >> 5);
    if (node >= NN) return;
    int lane = threadIdx.x & 31;
    size_t mo = (size_t)node * CC + lane * 4;
    float4 a3 = *(const float4*)(x3 + mo);
    float4 a4 = *(const float4*)(x4 + mo);
    float n3 = __ldg(g_n2a + node);
    float n4 = __ldg(g_n2b + node), s4 = __ldg(g_s1b + node);
    int st = g_ptr[node], en = g_ptr[node + 1];
    float4 cc = make_float4(0.f, 0.f, 0.f, 0.f), ce = cc;
    int e = st;
    for (; e + 1 < en; e += 2) {
        int j0 = __ldg(g_adj + e), j1 = __ldg(g_adj + e + 1);
        size_t o0 = (size_t)j0 * CC + lane * 4, o1 = (size_t)j1 * CC + lane * 4;
        float4 b30 = *(const float4*)(x3 + o0);
        float4 b31 = *(const float4*)(x3 + o1);
        float4 b40 = *(const float4*)(x4 + o0);
        float4 b41 = *(const float4*)(x4 + o1);
        float d30 = a3.x * b30.x + a3.y * b30.y + a3.z * b30.z + a3.w * b30.w;
        float d31 = a3.x * b31.x + a3.y * b31.y + a3.z * b31.z + a3.w * b31.w;
        float d40 = a4.x * b40.x + a4.y * b40.y + a4.z * b40.z + a4.w * b40.w;
        float d41 = a4.x * b41.x + a4.y * b41.y + a4.z * b41.z + a4.w * b41.w;
#pragma unroll
        for (int o = 16; o; o >>= 1) {
            d30 += __shfl_xor_sync(0xFFFFFFFFu, d30, o);
            d31 += __shfl_xor_sync(0xFFFFFFFFu, d31, o);
            d40 += __shfl_xor_sync(0xFFFFFFFFu, d40, o);
            d41 += __shfl_xor_sync(0xFFFFFFFFu, d41, o);
        }
        float nb30 = __ldg(g_n2a + j0), nb31 = __ldg(g_n2a + j1);
        float nb40 = __ldg(g_n2b + j0), nb41 = __ldg(g_n2b + j1);
        float sb40 = __ldg(g_s1b + j0), sb41 = __ldg(g_s1b + j1);
        float c0 = d30 / fmaxf(sqrtf(n3 * nb30), 1e-8f);
        float c1 = d31 / fmaxf(sqrtf(n3 * nb31), 1e-8f);
        float t0 = n4 + nb40 - 2.f * d40 + 2e-6f * (s4 - sb40) + 1.28e-10f;
        float t1 = n4 + nb41 - 2.f * d41 + 2e-6f * (s4 - sb41) + 1.28e-10f;
        float u0 = sqrtf(fmaxf(t0, 0.f)), u1 = sqrtf(fmaxf(t1, 0.f));
        cc.x += c0 * b30.x + c1 * b31.x; cc.y += c0 * b30.y + c1 * b31.y;
        cc.z += c0 * b30.z + c1 * b31.z; cc.w += c0 * b30.w + c1 * b31.w;
        ce.x += u0 * b40.x + u1 * b41.x; ce.y += u0 * b40.y + u1 * b41.y;
        ce.z += u0 * b40.z + u1 * b41.z; ce.w += u0 * b40.w + u1 * b41.w;
    }
    if (e < en) {
        int j0 = __ldg(g_adj + e);
        size_t o0 = (size_t)j0 * CC + lane * 4;
        float4 b30 = *(const float4*)(x3 + o0);
        float4 b40 = *(const float4*)(x4 + o0);
        float d30 = a3.x * b30.x + a3.y * b30.y + a3.z * b30.z + a3.w * b30.w;
        float d40 = a4.x * b40.x + a4.y * b40.y + a4.z * b40.z + a4.w * b40.w;
#pragma unroll
        for (int o = 16; o; o >>= 1) {
            d30 += __shfl_xor_sync(0xFFFFFFFFu, d30, o);
            d40 += __shfl_xor_sync(0xFFFFFFFFu, d40, o);
        }
        float nb30 = __ldg(g_n2a + j0);
        float nb40 = __ldg(g_n2b + j0), sb40 = __ldg(g_s1b + j0);
        float c0 = d30 / fmaxf(sqrtf(n3 * nb30), 1e-8f);
        float t0 = n4 + nb40 - 2.f * d40 + 2e-6f * (s4 - sb40) + 1.28e-10f;
        float u0 = sqrtf(fmaxf(t0, 0.f));
        cc.x += c0 * b30.x; cc.y += c0 * b30.y; cc.z += c0 * b30.z; cc.w += c0 * b30.w;
        ce.x += u0 * b40.x; ce.y += u0 * b40.y; ce.z += u0 * b40.z; ce.w += u0 * b40.w;
    }
    float inv = 1.f / fmaxf((float)(en - st), 1.f);
    cc.x *= inv; cc.y *= inv; cc.z *= inv; cc.w *= inv;
    ce.x *= inv; ce.y *= inv; ce.z *= inv; ce.w *= inv;
    *(float4*)(g_aggc + mo) = cc;
    *(float4*)(g_agge + mo) = ce;
}

// ---------------- gemm_one: O = A@W + bias ----------------
__global__ void __launch_bounds__(256, 2) gemm_one(
    const float* __restrict__ A, int w, const float* __restrict__ bias,
    float* __restrict__ O)
{
    extern __shared__ char sm[];
    int tid = threadIdx.x, lane = tid & 31, wid = tid >> 5;
    int bm = blockIdx.x * 128;
    uint32_t smb = smem_u32(sm);
    float* sbias = (float*)sm;
    if (tid < 128) sbias[tid] = bias[tid];

    float acc[16][4];
#pragma unroll
    for (int i = 0; i < 16; ++i)
#pragma unroll
        for (int j = 0; j < 4; ++j) acc[i][j] = 0.f;

    const int wm = (wid & 3) * 32, wn = (wid >> 2) * 64;
    WC32 wc; wc32_init(wc, wm, wn, lane);

    convA128(sm, A, bm, tid);
    gemm_pass(sm, smb, w, wc, tid, acc);

    int g = lane >> 2, tg = lane & 3;
#pragma unroll
    for (int mt = 0; mt < 2; ++mt) {
        int m0 = bm + wm + mt * 16 + g;
#pragma unroll
        for (int nt = 0; nt < 8; ++nt) {
            int cl = wn + nt * 8 + tg * 2;
            float b0 = sbias[cl], b1 = sbias[cl + 1];
            int idx = mt * 8 + nt;
            if (m0 < NN) {
                float2 v;
                v.x = acc[idx][0] + b0; v.y = acc[idx][1] + b1;
                *(float2*)(O + (size_t)m0 * CC + cl) = v;
            }
            if (m0 + 8 < NN) {
                float2 v;
                v.x = acc[idx][2] + b0; v.y = acc[idx][3] + b1;
                *(float2*)(O + (size_t)(m0 + 8) * CC + cl) = v;
            }
        }
    }
}

// ---------------- gemm_cadd: O[br] = relu(agg[br] @ W + Cadd) ----------------
__global__ void __launch_bounds__(256, 2) gemm_cadd(
    int w, const float* __restrict__ Cadd,
    float* __restrict__ Oc, float* __restrict__ Oe)
{
    extern __shared__ char sm[];
    int tid = threadIdx.x, lane = tid & 31, wid = tid >> 5;
    int bm = blockIdx.x * 128, br = blockIdx.y;
    uint32_t smb = smem_u32(sm);
    const float* A = br ? g_agge : g_aggc;
    float* O = br ? Oe : Oc;

    float acc[16][4];
#pragma unroll
    for (int i = 0; i < 16; ++i)
#pragma unroll
        for (int j = 0; j < 4; ++j) acc[i][j] = 0.f;

    const int wm = (wid & 3) * 32, wn = (wid >> 2) * 64;
    WC32 wc; wc32_init(wc, wm, wn, lane);

    convA128(sm, A, bm, tid);
    gemm_pass(sm, smb, w, wc, tid, acc);

    int g = lane >> 2, tg = lane & 3;
#pragma unroll
    for (int mt = 0; mt < 2; ++mt) {
        int m0 = bm + wm + mt * 16 + g;
#pragma unroll
        for (int nt = 0; nt < 8; ++nt) {
            int cl = wn + nt * 8 + tg * 2;
            int idx = mt * 8 + nt;
            if (m0 < NN) {
                float2 cv = *(const float2*)(Cadd + (size_t)m0 * CC + cl);
                float2 v;
                v.x = fmaxf(acc[idx][0] + cv.x, 0.f);
                v.y = fmaxf(acc[idx][1] + cv.y, 0.f);
                *(float2*)(O + (size_t)m0 * CC + cl) = v;
            }
            if (m0 + 8 < NN) {
                float2 cv = *(const float2*)(Cadd + (size_t)(m0 + 8) * CC + cl);
                float2 v;
                v.x = fmaxf(acc[idx][2] + cv.x, 0.f);
                v.y = fmaxf(acc[idx][3] + cv.y, 0.f);
                *(float2*)(O + (size_t)(m0 + 8) * CC + cl) = v;
            }
        }
    }
}

// ---------------- L1 fused GEMM: O[br] = A1@W1 + agg[br]@W2 + bias ----------------
__global__ void __launch_bounds__(256, 2) gemm_two(
    const float* __restrict__ A1c, const float* __restrict__ A1e,
    int w1, int w2, const float* __restrict__ bias,
    float* __restrict__ Oc, float* __restrict__ Oe)
{
    extern __shared__ char sm[];
    int tid = threadIdx.x, lane = tid & 31, wid = tid >> 5;
    int bm = blockIdx.x * 128, br = blockIdx.y;
    uint32_t smb = smem_u32(sm);
    float* sbias = (float*)sm;
    if (tid < 128) sbias[tid] = bias[tid];
    const float* A1 = br ? A1e : A1c;
    const float* A2 = br ? g_agge : g_aggc;
    float* O = br ? Oe : Oc;

    float acc[16][4];
#pragma unroll
    for (int i = 0; i < 16; ++i)
#pragma unroll
        for (int j = 0; j < 4; ++j) acc[i][j] = 0.f;

    const int wm = (wid & 3) * 32, wn = (wid >> 2) * 64;
    WC32 wc; wc32_init(wc, wm, wn, lane);

    convA128(sm, A1, bm, tid);
    gemm_pass(sm, smb, w1, wc, tid, acc);
    __syncthreads();
    convA128(sm, A2, bm, tid);
    gemm_pass(sm, smb, w2, wc, tid, acc);

    int g = lane >> 2, tg = lane & 3;
#pragma unroll
    for (int mt = 0; mt < 2; ++mt) {
        int m0 = bm + wm + mt * 16 + g;
#pragma unroll
        for (int nt = 0; nt < 8; ++nt) {
            int cl = wn + nt * 8 + tg * 2;
            float b0 = sbias[cl], b1 = sbias[cl + 1];
            int idx = mt * 8 + nt;
            if (m0 < NN) {
                float2 v;
                v.x = acc[idx][0] + b0; v.y = acc[idx][1] + b1;
                *(float2*)(O + (size_t)m0 * CC + cl) = v;
            }
            if (m0 + 8 < NN) {
                float2 v;
                v.x = acc[idx][2] + b0; v.y = acc[idx][3] + b1;
                *(float2*)(O + (size_t)(m0 + 8) * CC + cl) = v;
            }
        }
    }
}

// ---------------- attention: tensor-core logits + softmax blend ----------------
__global__ void __launch_bounds__(256) att_tc(
    const float* __restrict__ x1, const float* __restrict__ x2,
    const float* __restrict__ x3, const float* __restrict__ x4,
    const float* __restrict__ ab1, const float* __restrict__ aW2,
    float* __restrict__ emb)
{
    extern __shared__ char sm[];
    int tid = threadIdx.x, lane = tid & 31, wid = tid >> 5;
    int bm = blockIdx.x * 128;
    uint32_t smb = smem_u32(sm);
    float* b1s = (float*)sm;
    float* w2s = (float*)(sm + 256);
    float* wsm = (float*)(sm + SA_WSM);
    if (tid < 64) { b1s[tid] = ab1[tid]; w2s[tid] = aW2[tid]; }
    {
        const uint4* sh = (const uint4*)g_wt[4][0];
        const uint4* sl = (const uint4*)g_wt[4][1];
        uint4* dh = (uint4*)(sm + SA_WH);
        uint4* dl = (uint4*)(sm + SA_WL);
#pragma unroll
        for (int i = 0; i < 4; ++i) {
            dh[tid + i * 256] = sh[tid + i * 256];
            dl[tid + i * 256] = sl[tid + i * 256];
        }
    }
    const float* Xb[4] = {x1, x2, x3, x4};
    int wm = wid * 16;
    WC16 wc; wc16_init(wc, wm, lane);
    int g = lane >> 2, tg = lane & 3;
    for (int b = 0; b < 4; ++b) {
        __syncthreads();
        convA128(sm, Xb[b], bm, tid);
        __syncthreads();
        float acc[8][4];
#pragma unroll
        for (int i = 0; i < 8; ++i)
#pragma unroll
            for (int j = 0; j < 4; ++j) acc[i][j] = 0.f;
        term_pair16(smb + S_AH, smb + S_AL, smb + SA_WH, wc, acc);
        term_one16(smb + S_AH, smb + SA_WL, wc, acc);
        float w0 = 0.f, w1p = 0.f;
#pragma unroll
        for (int nt = 0; nt < 8; ++nt) {
            int cl = nt * 8 + tg * 2;
            w0  += tanha(acc[nt][0] + b1s[cl]) * w2s[cl]
                 + tanha(acc[nt][1] + b1s[cl + 1]) * w2s[cl + 1];
            w1p += tanha(acc[nt][2] + b1s[cl]) * w2s[cl]
                 + tanha(acc[nt][3] + b1s[cl + 1]) * w2s[cl + 1];
        }
        w0 += __shfl_xor_sync(0xFFFFFFFFu, w0, 1);
        w0 += __shfl_xor_sync(0xFFFFFFFFu, w0, 2);
        w1p += __shfl_xor_sync(0xFFFFFFFFu, w1p, 1);
        w1p += __shfl_xor_sync(0xFFFFFFFFu, w1p, 2);
        if (tg == 0) {
            wsm[(wm + g) * 4 + b] = w0;
            wsm[(wm + 8 + g) * 4 + b] = w1p;
        }
    }
    __syncthreads();
    int row = tid >> 1, half = tid & 1;
    int gr = bm + row;
    if (gr >= NN) return;
    float l0 = wsm[row * 4 + 0], l1 = wsm[row * 4 + 1];
    float l2 = wsm[row * 4 + 2], l3 = wsm[row * 4 + 3];
    float m = fmaxf(fmaxf(l0, l1), fmaxf(l2, l3));
    float e0 = __expf(l0 - m), e1 = __expf(l1 - m), e2 = __expf(l2 - m), e3 = __expf(l3 - m);
    float inv = 1.f / (e0 + e1 + e2 + e3);
    float be0 = e0 * inv, be1 = e1 * inv, be2 = e2 * inv, be3 = e3 * inv;
    size_t base = (size_t)gr * CC + half * 64;
#pragma unroll
    for (int c = 0; c < 16; ++c) {
        float4 z0 = *(const float4*)(x1 + base + c * 4);
        float4 z1 = *(const float4*)(x2 + base + c * 4);
        float4 z2 = *(const float4*)(x3 + base + c * 4);
        float4 z3 = *(const float4*)(x4 + base + c * 4);
        float4 o;
        o.x = be0 * z0.x + be1 * z1.x + be2 * z2.x + be3 * z3.x;
        o.y = be0 * z0.y + be1 * z1.y + be2 * z2.y + be3 * z3.y;
        o.z = be0 * z0.z + be1 * z1.z + be2 * z2.z + be3 * z3.z;
        o.w = be0 * z0.w + be1 * z1.w + be2 * z2.w + be3 * z3.w;
        *(float4*)(emb + base + c * 4) = o;
    }
}

// ---------------- launch ----------------
extern "C" void kernel_launch(void* const* d_in, const int* in_sizes, int n_in,
                              void* d_out, int out_size)
{
    const float* x   = (const float*)d_in[0];
    const int*   row = (const int*)d_in[1];
    const int*   col = (const int*)d_in[2];
    const float* Wl0 = (const float*)d_in[3];
    const float* bl0 = (const float*)d_in[4];
    const float* Wr0 = (const float*)d_in[5];
    const float* Wl1 = (const float*)d_in[6];
    const float* bl1 = (const float*)d_in[7];
    const float* Wr1 = (const float*)d_in[8];
    const float* aW1 = (const float*)d_in[9];
    const float* ab1 = (const float*)d_in[10];
    const float* aW2 = (const float*)d_in[11];

    float* out = (float*)d_out;
    float* x3  = out + (size_t)NN * CC;
    float* x4  = out + 2 * (size_t)NN * CC;

    float *x1, *x2, *n2a, *s1a;
    int* cnt;
    cudaGetSymbolAddress((void**)&x1,  g_x1);
    cudaGetSymbolAddress((void**)&x2,  g_x2);
    cudaGetSymbolAddress((void**)&n2a, g_n2a);
    cudaGetSymbolAddress((void**)&s1a, g_s1a);
    cudaGetSymbolAddress((void**)&cnt, g_cnt);

    cudaFuncSetAttribute(gemm_one,  cudaFuncAttributeMaxDynamicSharedMemorySize, SMEM_G);
    cudaFuncSetAttribute(gemm_cadd, cudaFuncAttributeMaxDynamicSharedMemorySize, SMEM_G);
    cudaFuncSetAttribute(gemm_two,  cudaFuncAttributeMaxDynamicSharedMemorySize, SMEM_G);
    cudaFuncSetAttribute(att_tc,    cudaFuncAttributeMaxDynamicSharedMemorySize, SMEM_A);

    const int gE = (EE + 255) / 256;       // 3125
    const int gN = (NN + 7) / 8;           // 6250
    const int gG = (NN + 127) / 128;       // 391
    const dim3 gG2(gG, 2);

    // CSR + stats first (also places agg1 in the ncu capture slot)
    cudaMemsetAsync(cnt, 0, NN * sizeof(int));
    hist_k<<<gE, 256>>>(row);
    scan_k<<<1, 1024>>>();
    fill_k<<<gE, 256>>>(row, col);
    pre_k<<<gN, 256>>>(x, n2a, s1a);
    agg1_k<<<gN, 256>>>(x);

    // weights -> bf16 hi/lo tiles, then layer-0 GEMMs
    convw_k<<<dim3(5, 4), 256>>>(Wr0, Wl0, Wr1, Wl1, aW1);
    gemm_one<<<gG, 256, SMEM_G>>>(x, 0, bl0, x1);              // xwr = x@Wr0 + bl0
    gemm_cadd<<<gG2, 256, SMEM_G>>>(1, x1, x3, x4);            // relu(agg@Wl0 + xwr)

    // layer 1
    pre2_k<<<gN, 256>>>(x3, x4);
    agg2_k<<<gN, 256>>>(x3, x4);
    gemm_two<<<gG2, 256, SMEM_G>>>(x3, x4, 2, 3, bl1, x1, x2); // x1/x2 outputs

    // attention
    att_tc<<<gG, 256, SMEM_A>>>(x1, x2, x3, x4, ab1, aW2, out);
}